// round 2
// baseline (speedup 1.0000x reference)
#include <cuda_runtime.h>
#include <math.h>

// ---------------- problem constants ----------------
constexpr int B_  = 16;
constexpr int D_  = 256;
constexpr int NH_ = 512;
constexpr int NV_ = 256;
constexpr int W_  = 768;          // NH + NV
constexpr int L_  = 4;
constexpr int H_  = 8;
constexpr int A_  = 64;
constexpr int HA_ = 512;
constexpr int M_  = 512;
constexpr int R_  = 128;
constexpr int GHA_ = L_ * H_ * A_;   // 2048
constexpr float EPS_   = 1e-5f;
constexpr float SCALE_ = 0.125f;     // A^-0.5

// ---------------- device scratch (no allocs allowed) ----------------
__device__ float g_ki   [B_ * W_ * (D_ + 1)];
__device__ float g_kwT  [(D_ + 1) * GHA_];
__device__ float g_vwT  [(D_ + 1) * GHA_];
__device__ float g_att  [B_ * NV_ * HA_];
__device__ float g_keys [(size_t)B_ * W_ * GHA_];
__device__ float g_vals [(size_t)B_ * W_ * GHA_];
__device__ float g_scores[(size_t)B_ * H_ * NV_ * W_];
__device__ float g_res  [B_ * NV_ * HA_];
__device__ float g_ff1  [B_ * NV_ * M_];
__device__ float g_ff2  [B_ * NV_ * M_];
__device__ float g_logits[B_ * NV_ * R_];

// ---------------- build ki = [hist||u ; pred||u]  [B, W, 257] ----------------
__global__ void build_ki(const float* __restrict__ hist, const float* __restrict__ hu,
                         const float* __restrict__ pred, const float* __restrict__ pu) {
    int idx = blockIdx.x * blockDim.x + threadIdx.x;
    const int total = B_ * W_ * (D_ + 1);
    if (idx >= total) return;
    int d = idx % (D_ + 1);
    int w = (idx / (D_ + 1)) % W_;
    int b = idx / ((D_ + 1) * W_);
    float v;
    if (d < D_) {
        v = (w < NH_) ? hist[((size_t)(b * NH_ + w)) * D_ + d]
                      : pred[((size_t)(b * NV_ + (w - NH_))) * D_ + d];
    } else {
        v = (w < NH_) ? hu[b * NH_ + w] : pu[b * NV_ + (w - NH_)];
    }
    g_ki[idx] = v;
}

// key_w [L,H,257,A] -> [257, L*H*A]
__global__ void transpose_w(const float* __restrict__ src, float* __restrict__ dst) {
    int idx = blockIdx.x * blockDim.x + threadIdx.x;
    const int total = (D_ + 1) * GHA_;
    if (idx >= total) return;
    int c = idx % GHA_;
    int d = idx / GHA_;
    int g = c >> 6;        // l*H + h
    int a = c & 63;
    dst[idx] = src[((size_t)(g * (D_ + 1) + d)) * A_ + a];
}

// ======================================================================
// Big-tile SGEMM engine.
// C[M x N] = A[M x K] @ op(B)[K x N] (+bias)(+relu)(+mask*scale)(+residual)
// Block tile 128 x BN (BN = 16*TN), 256 threads, 8xTN per thread,
// double-buffered SMEM via register staging, one sync per K-tile.
// Batched via blockIdx.z with composite (z/Hdiv, z%Hdiv) strides.
// ======================================================================
template <int TN, bool TRANSB, bool RELU, bool MASKED, bool KTRIM, bool RESADD>
__global__ __launch_bounds__(256)
void gemm_big(const float* __restrict__ A, const float* __restrict__ Bm,
              const float* __restrict__ bias, const float* __restrict__ resid,
              float* __restrict__ C,
              int Mr, int N, int K, int lda, int ldb, int ldc,
              long long sA1, long long sA2, long long sB1, long long sB2,
              long long sC1, long long sC2, int Hdiv)
{
    constexpr int BN = TN * 16;
    const int z = blockIdx.z;
    const long long zq = z / Hdiv, zr = z % Hdiv;
    A  += zq * sA1 + zr * sA2;
    Bm += zq * sB1 + zr * sB2;
    const long long coff = zq * sC1 + zr * sC2;
    C += coff;
    const float* res = RESADD ? (resid + coff) : nullptr;

    const int bm = blockIdx.y * 128;
    const int bn = blockIdx.x * BN;
    const int t  = threadIdx.x;
    const int ty = t >> 4, tx = t & 15;

    if (MASKED && bn >= NH_ + bm + 128) {
        // entire tile masked -> -inf
#pragma unroll
        for (int r = 0; r < 8; r++) {
            int m = bm + ty * 8 + r;
            if (m >= Mr) continue;
#pragma unroll
            for (int c = 0; c < TN; c++) {
                int n = bn + tx * TN + c;
                if (n < N) C[(size_t)m * ldc + n] = -INFINITY;
            }
        }
        return;
    }

    __shared__ float As[2][16][132];
    __shared__ float Bs[2][16][BN + 4];

    int Kuse = K;
    if (KTRIM) Kuse = min(K, NH_ + bm + 128);
    const int KT = (Kuse + 15) >> 4;

    float ra[8], rb[8];

    // A loader: thread -> (row am, 8 consecutive k starting at ak)
    const int am = t >> 1, ak = (t & 1) * 8;
    // B loader (non-transposed): thread -> (row bk, TN consecutive n)
    const int bk = t >> 4, bnn = (t & 15) * TN;
    // B loader (transposed, BN==128 only): thread -> (col tbn, 8 consecutive k)
    const int tbn = t >> 1, tbk = (t & 1) * 8;

    auto load_tile = [&](int kt) {
        const int k0 = kt << 4;
#pragma unroll
        for (int j = 0; j < 8; j++) {
            int kk = k0 + ak + j;
            ra[j] = (kk < Kuse && (bm + am) < Mr)
                    ? A[(size_t)(bm + am) * lda + kk] : 0.f;
        }
        if (TRANSB) {
#pragma unroll
            for (int j = 0; j < 8; j++) {
                int kk = k0 + tbk + j;
                rb[j] = (kk < Kuse && (bn + tbn) < N)
                        ? Bm[(size_t)(bn + tbn) * ldb + kk] : 0.f;
            }
        } else {
#pragma unroll
            for (int j = 0; j < TN; j++) {
                int nn = bn + bnn + j;
                rb[j] = ((k0 + bk) < Kuse && nn < N)
                        ? Bm[(size_t)(k0 + bk) * ldb + nn] : 0.f;
            }
        }
    };
    auto store_tile = [&](int p) {
#pragma unroll
        for (int j = 0; j < 8; j++) As[p][ak + j][am] = ra[j];
        if (TRANSB) {
#pragma unroll
            for (int j = 0; j < 8; j++) Bs[p][tbk + j][tbn] = rb[j];
        } else {
#pragma unroll
            for (int j = 0; j < TN; j++) Bs[p][bk][bnn + j] = rb[j];
        }
    };

    float acc[8][TN] = {};
    load_tile(0);
    store_tile(0);
    __syncthreads();
    int p = 0;
    for (int kt = 0; kt < KT; kt++) {
        if (kt + 1 < KT) load_tile(kt + 1);
#pragma unroll
        for (int k = 0; k < 16; k++) {
            float a[8], b[TN];
#pragma unroll
            for (int r = 0; r < 8; r++) a[r] = As[p][k][ty * 8 + r];
#pragma unroll
            for (int c = 0; c < TN; c++) b[c] = Bs[p][k][tx * TN + c];
#pragma unroll
            for (int r = 0; r < 8; r++)
#pragma unroll
                for (int c = 0; c < TN; c++)
                    acc[r][c] = fmaf(a[r], b[c], acc[r][c]);
        }
        if (kt + 1 < KT) {
            store_tile(p ^ 1);
            __syncthreads();
            p ^= 1;
        }
    }

#pragma unroll
    for (int r = 0; r < 8; r++) {
        int m = bm + ty * 8 + r;
        if (m >= Mr) continue;
#pragma unroll
        for (int c = 0; c < TN; c++) {
            int n = bn + tx * TN + c;
            if (n >= N) continue;
            float v = acc[r][c];
            if (MASKED) {
                v = (n >= NH_ + m) ? -INFINITY : v * SCALE_;
            } else {
                if (bias) v += bias[n];
                if (RELU) v = fmaxf(v, 0.f);
                if (RESADD) v += res[(size_t)m * ldc + n];
            }
            C[(size_t)m * ldc + n] = v;
        }
    }
}

// ---------------- softmax over W (row-wise, handles -inf tail) ----------------
__global__ void softmax_rows() {
    const int row = blockIdx.x;  // B*H*NV
    float* p = g_scores + (size_t)row * W_;
    const int t = threadIdx.x;   // 128
    float vals[6];
    float m = -INFINITY;
#pragma unroll
    for (int i = 0; i < 6; i++) { vals[i] = p[t + i * 128]; m = fmaxf(m, vals[i]); }
    __shared__ float red[128];
    red[t] = m; __syncthreads();
    for (int s = 64; s > 0; s >>= 1) { if (t < s) red[t] = fmaxf(red[t], red[t + s]); __syncthreads(); }
    m = red[0];
    __syncthreads();
    float sum = 0.f;
#pragma unroll
    for (int i = 0; i < 6; i++) { vals[i] = __expf(vals[i] - m); sum += vals[i]; }
    red[t] = sum; __syncthreads();
    for (int s = 64; s > 0; s >>= 1) { if (t < s) red[t] += red[t + s]; __syncthreads(); }
    float inv = 1.f / red[0];
#pragma unroll
    for (int i = 0; i < 6; i++) p[t + i * 128] = vals[i] * inv;
}

// ---------------- layernorm: out = g * norm(base + delta) + beta ----------------
__global__ void ln_kernel(const float* __restrict__ base, const float* __restrict__ delta,
                          const float* __restrict__ gamma, const float* __restrict__ beta,
                          float* __restrict__ out) {
    const int row = blockIdx.x;  // B*NV
    const int t = threadIdx.x;   // 256
    const float* br = base + (size_t)row * HA_;
    float x0 = br[t];
    float x1 = br[t + 256];
    if (delta) {
        const float* dr = delta + (size_t)row * HA_;
        x0 += dr[t];
        x1 += dr[t + 256];
    }
    __shared__ float red[256];
    red[t] = x0 + x1; __syncthreads();
    for (int s = 128; s > 0; s >>= 1) { if (t < s) red[t] += red[t + s]; __syncthreads(); }
    float mean = red[0] * (1.f / HA_);
    __syncthreads();
    float d0 = x0 - mean, d1 = x1 - mean;
    red[t] = d0 * d0 + d1 * d1; __syncthreads();
    for (int s = 128; s > 0; s >>= 1) { if (t < s) red[t] += red[t + s]; __syncthreads(); }
    float inv = rsqrtf(red[0] * (1.f / HA_) + EPS_);
    out[(size_t)row * HA_ + t]       = gamma[t]       * (d0 * inv) + beta[t];
    out[(size_t)row * HA_ + t + 256] = gamma[t + 256] * (d1 * inv) + beta[t + 256];
}

// ---------------- final loss reduction (deterministic, one CTA per batch) ----------------
__global__ void loss_kernel(const float* __restrict__ pu, float* __restrict__ out) {
    const int b = blockIdx.x;
    const int t = threadIdx.x;           // 256 = 8 warps
    const int warp = t >> 5, lane = t & 31;
    const float LOG_R = logf((float)R_);
    float accum = 0.f;
    for (int v = 1 + warp; v < NV_; v += 8) {
        const float* lr = g_logits + ((size_t)(b * NV_ + v)) * R_;
        float lv[4];
        float m = -INFINITY;
#pragma unroll
        for (int i = 0; i < 4; i++) { lv[i] = lr[lane + i * 32]; m = fmaxf(m, lv[i]); }
#pragma unroll
        for (int o = 16; o > 0; o >>= 1) m = fmaxf(m, __shfl_xor_sync(0xffffffffu, m, o));
        float se = 0.f;
#pragma unroll
        for (int i = 0; i < 4; i++) se += expf(lv[i] - m);
#pragma unroll
        for (int o = 16; o > 0; o >>= 1) se += __shfl_xor_sync(0xffffffffu, se, o);
        if (lane == 0) {
            float lse = m + logf(se);
            int tgt = (int)floorf(pu[b * NV_ + v] * (float)R_);
            tgt = min(max(tgt, 0), R_ - 1);
            accum += lse - lr[tgt] - LOG_R;
        }
    }
    __shared__ float red[8];
    if (lane == 0) red[warp] = accum;
    __syncthreads();
    if (t == 0) {
        float s = 0.f;
#pragma unroll
        for (int i = 0; i < 8; i++) s += red[i];
        out[b] = s;
    }
}

// ---------------- host launch ----------------
static float* sym_addr(const void* sym) {
    void* p = nullptr;
    cudaGetSymbolAddress(&p, sym);
    return (float*)p;
}

extern "C" void kernel_launch(void* const* d_in, const int* in_sizes, int n_in,
                              void* d_out, int out_size) {
    (void)in_sizes; (void)n_in; (void)out_size;
    const float* hist  = (const float*)d_in[0];
    const float* hu    = (const float*)d_in[1];
    const float* pred  = (const float*)d_in[2];
    const float* pu    = (const float*)d_in[3];
    const float* ds_w  = (const float*)d_in[4];
    const float* ds_b  = (const float*)d_in[5];
    const float* key_w = (const float*)d_in[6];
    const float* key_b = (const float*)d_in[7];
    const float* val_w = (const float*)d_in[8];
    const float* val_b = (const float*)d_in[9];
    const float* ln1_g = (const float*)d_in[10];
    const float* ln1_b = (const float*)d_in[11];
    const float* ln2_g = (const float*)d_in[12];
    const float* ln2_b = (const float*)d_in[13];
    const float* ff_w1 = (const float*)d_in[14];
    const float* ff_b1 = (const float*)d_in[15];
    const float* ff_w2 = (const float*)d_in[16];
    const float* ff_b2 = (const float*)d_in[17];
    const float* ff_w3 = (const float*)d_in[18];
    const float* ff_b3 = (const float*)d_in[19];
    const float* de_w  = (const float*)d_in[20];
    const float* de_b  = (const float*)d_in[21];
    float* out = (float*)d_out;

    float* ki    = sym_addr(g_ki);
    float* kwT   = sym_addr(g_kwT);
    float* vwT   = sym_addr(g_vwT);
    float* att   = sym_addr(g_att);
    float* keys  = sym_addr(g_keys);
    float* vals  = sym_addr(g_vals);
    float* scr   = sym_addr(g_scores);
    float* res   = sym_addr(g_res);
    float* ff1   = sym_addr(g_ff1);
    float* ff2   = sym_addr(g_ff2);
    float* logit = sym_addr(g_logits);

    const int BNV = B_ * NV_;          // 4096
    const int BW  = B_ * W_;           // 12288

    // 1. inputs
    {
        int total = B_ * W_ * (D_ + 1);
        build_ki<<<(total + 255) / 256, 256>>>(hist, hu, pred, pu);
    }
    {
        int total = (D_ + 1) * GHA_;
        transpose_w<<<(total + 255) / 256, 256>>>(key_w, kwT);
        transpose_w<<<(total + 255) / 256, 256>>>(val_w, vwT);
    }
    // 2. att = pred @ ds_w + ds_b   [4096, 512] K=256
    gemm_big<8, false, false, false, false, false><<<dim3(HA_ / 128, BNV / 128, 1), 256>>>(
        pred, ds_w, ds_b, nullptr, att, BNV, HA_, D_, D_, HA_, HA_,
        0, 0, 0, 0, 0, 0, 1);
    // 3. keys / vals = ki @ kwT + bias  [12288, 2048] K=257
    gemm_big<8, false, false, false, false, false><<<dim3(GHA_ / 128, BW / 128, 1), 256>>>(
        ki, kwT, key_b, nullptr, keys, BW, GHA_, D_ + 1, D_ + 1, GHA_, GHA_,
        0, 0, 0, 0, 0, 0, 1);
    gemm_big<8, false, false, false, false, false><<<dim3(GHA_ / 128, BW / 128, 1), 256>>>(
        ki, vwT, val_b, nullptr, vals, BW, GHA_, D_ + 1, D_ + 1, GHA_, GHA_,
        0, 0, 0, 0, 0, 0, 1);

    const long long sQ1 = (long long)NV_ * HA_;      // per-b stride of att
    const long long sKV1 = (long long)W_ * GHA_;     // per-b stride of keys/vals
    const long long sS  = (long long)NV_ * W_;       // per-(b,h) stride of scores
    const long long sO1 = (long long)NV_ * HA_;      // per-b stride of res/att out

    // 4. layers
    for (int l = 0; l < L_; l++) {
        // scores[b,h,v,w] = mask(-inf) or scale * Q . K  — batched over z=b*8+h
        gemm_big<8, true, false, true, false, false><<<dim3(W_ / 128, NV_ / 128, B_ * H_), 256>>>(
            att, keys + l * H_ * A_, nullptr, nullptr, scr,
            NV_, W_, A_, HA_, GHA_, W_,
            sQ1, (long long)A_, sKV1, (long long)A_, 8 * sS, sS, H_);
        softmax_rows<<<B_ * H_ * NV_, 128>>>();
        // res[b,v,h*64+j] = att + P @ V — batched, K trimmed to causal bound
        gemm_big<4, false, false, false, true, true><<<dim3(1, NV_ / 128, B_ * H_), 256>>>(
            scr, vals + l * H_ * A_, nullptr, att, res,
            NV_, A_, W_, W_, GHA_, HA_,
            8 * sS, sS, sKV1, (long long)A_, sO1, (long long)A_, H_);
        ln_kernel<<<BNV, 256>>>(res, nullptr, ln1_g + l * HA_, ln1_b + l * HA_, att);
        gemm_big<8, false, true, false, false, false><<<dim3(M_ / 128, BNV / 128, 1), 256>>>(
            att, ff_w1 + (size_t)l * HA_ * M_, ff_b1 + l * M_, nullptr, ff1,
            BNV, M_, HA_, HA_, M_, M_, 0, 0, 0, 0, 0, 0, 1);
        gemm_big<8, false, true, false, false, false><<<dim3(M_ / 128, BNV / 128, 1), 256>>>(
            ff1, ff_w2 + (size_t)l * M_ * M_, ff_b2 + l * M_, nullptr, ff2,
            BNV, M_, M_, M_, M_, M_, 0, 0, 0, 0, 0, 0, 1);
        gemm_big<8, false, false, false, false, false><<<dim3(HA_ / 128, BNV / 128, 1), 256>>>(
            ff2, ff_w3 + (size_t)l * M_ * HA_, ff_b3 + l * HA_, nullptr, res,
            BNV, HA_, M_, M_, HA_, HA_, 0, 0, 0, 0, 0, 0, 1);
        ln_kernel<<<BNV, 256>>>(att, res, ln2_g + l * HA_, ln2_b + l * HA_, att);
    }
    // 5. logits + loss
    gemm_big<8, false, false, false, false, false><<<dim3(1, BNV / 128, 1), 256>>>(
        att, de_w, de_b, nullptr, logit, BNV, R_, HA_, HA_, R_, R_,
        0, 0, 0, 0, 0, 0, 1);
    loss_kernel<<<B_, 256>>>(pu, out);
}

// round 3
// speedup vs baseline: 1.1674x; 1.1674x over previous
#include <cuda_runtime.h>
#include <math.h>
#include <stdint.h>

// ---------------- problem constants ----------------
constexpr int B_  = 16;
constexpr int D_  = 256;
constexpr int NH_ = 512;
constexpr int NV_ = 256;
constexpr int W_  = 768;          // NH + NV
constexpr int L_  = 4;
constexpr int H_  = 8;
constexpr int A_  = 64;
constexpr int HA_ = 512;
constexpr int M_  = 512;
constexpr int R_  = 128;
constexpr int GHA_ = L_ * H_ * A_;   // 2048
constexpr float EPS_   = 1e-5f;
constexpr float SCALE_ = 0.125f;     // A^-0.5

// ---------------- device scratch (no allocs allowed) ----------------
__device__ float g_ki   [B_ * W_ * (D_ + 1)];
__device__ float g_kwT  [(D_ + 1) * GHA_];
__device__ float g_vwT  [(D_ + 1) * GHA_];
__device__ float g_att  [B_ * NV_ * HA_];
__device__ float g_keys [(size_t)B_ * W_ * GHA_];
__device__ float g_vals [(size_t)B_ * W_ * GHA_];
__device__ float g_scores[(size_t)B_ * H_ * NV_ * W_];
__device__ float g_res  [B_ * NV_ * HA_];
__device__ float g_ff1  [B_ * NV_ * M_];
__device__ float g_ff2  [B_ * NV_ * M_];
__device__ float g_logits[B_ * NV_ * R_];

// ---------------- build ki = [hist||u ; pred||u]  [B, W, 257] ----------------
__global__ void build_ki(const float* __restrict__ hist, const float* __restrict__ hu,
                         const float* __restrict__ pred, const float* __restrict__ pu) {
    int idx = blockIdx.x * blockDim.x + threadIdx.x;
    const int total = B_ * W_ * (D_ + 1);
    if (idx >= total) return;
    int d = idx % (D_ + 1);
    int w = (idx / (D_ + 1)) % W_;
    int b = idx / ((D_ + 1) * W_);
    float v;
    if (d < D_) {
        v = (w < NH_) ? hist[((size_t)(b * NH_ + w)) * D_ + d]
                      : pred[((size_t)(b * NV_ + (w - NH_))) * D_ + d];
    } else {
        v = (w < NH_) ? hu[b * NH_ + w] : pu[b * NV_ + (w - NH_)];
    }
    g_ki[idx] = v;
}

// key_w [L,H,257,A] -> [257, L*H*A]
__global__ void transpose_w(const float* __restrict__ src, float* __restrict__ dst) {
    int idx = blockIdx.x * blockDim.x + threadIdx.x;
    const int total = (D_ + 1) * GHA_;
    if (idx >= total) return;
    int c = idx % GHA_;
    int d = idx / GHA_;
    int g = c >> 6;        // l*H + h
    int a = c & 63;
    dst[idx] = src[((size_t)(g * (D_ + 1) + d)) * A_ + a];
}

// ---------------- tf32 helpers ----------------
__device__ __forceinline__ void split_tf32(float x, uint32_t& hi, uint32_t& lo) {
    asm("cvt.rna.tf32.f32 %0, %1;" : "=r"(hi) : "f"(x));
    float h = __uint_as_float(hi);
    float l = x - h;
    asm("cvt.rna.tf32.f32 %0, %1;" : "=r"(lo) : "f"(l));
}

__device__ __forceinline__ void mma_tf32(float (&d)[4], const uint32_t (&a)[4],
                                         const uint32_t (&b)[2]) {
    asm volatile(
        "mma.sync.aligned.m16n8k8.row.col.f32.tf32.tf32.f32 "
        "{%0,%1,%2,%3},{%4,%5,%6,%7},{%8,%9},{%0,%1,%2,%3};"
        : "+f"(d[0]), "+f"(d[1]), "+f"(d[2]), "+f"(d[3])
        : "r"(a[0]), "r"(a[1]), "r"(a[2]), "r"(a[3]), "r"(b[0]), "r"(b[1]));
}

// ======================================================================
// Tensor-core GEMM (3xTF32, fp32-equivalent accuracy).
// C[M x N] = A[M x K] @ op(B)[K x N] (+bias)(+relu)(+mask*scale)(+residual)
// CTA tile 128x64, 8 warps (4m x 2n), warp tile 32x32 (2 mtiles x 4 ntiles
// of m16n8k8), K-tile 8, double-buffered hi/lo SMEM.
// Requires: M % 128 == 0, N % 64 == 0 (always true here); K guarded.
// Batched via blockIdx.z with composite (z/Hdiv, z%Hdiv) strides.
// ======================================================================
template <bool TRANSB, bool MASKED, bool RELU, bool KTRIM, bool RESADD>
__global__ __launch_bounds__(256)
void gemm_tc(const float* __restrict__ A, const float* __restrict__ Bm,
             const float* __restrict__ bias, const float* __restrict__ resid,
             float* __restrict__ C,
             int N, int K, int lda, int ldb, int ldc,
             long long sA1, long long sA2, long long sB1, long long sB2,
             long long sC1, long long sC2, int Hdiv)
{
    const int z = blockIdx.z;
    const long long zq = z / Hdiv, zr = z % Hdiv;
    A  += zq * sA1 + zr * sA2;
    Bm += zq * sB1 + zr * sB2;
    const long long coff = zq * sC1 + zr * sC2;
    C += coff;
    const float* res = RESADD ? (resid + coff) : nullptr;

    const int bm = blockIdx.y * 128;
    const int bn = blockIdx.x * 64;
    const int t    = threadIdx.x;
    const int lane = t & 31;
    const int warp = t >> 5;
    const int wm = (warp >> 1) * 32;   // warp m offset in tile
    const int wn = (warp & 1) * 32;    // warp n offset in tile
    const int fc = lane & 3;           // frag col group
    const int fg = lane >> 2;          // frag row group

    if (MASKED && bn >= NH_ + bm + 128) {
        // whole tile masked
        float2 ninf = make_float2(-INFINITY, -INFINITY);
#pragma unroll
        for (int mt = 0; mt < 2; mt++) {
            int m0 = bm + wm + mt * 16 + fg;
#pragma unroll
            for (int nt = 0; nt < 4; nt++) {
                int n0 = bn + wn + nt * 8 + fc * 2;
                *(float2*)(C + (size_t)m0 * ldc + n0) = ninf;
                *(float2*)(C + (size_t)(m0 + 8) * ldc + n0) = ninf;
            }
        }
        return;
    }

    __shared__ uint32_t Ah[2][8][136], Al[2][8][136];   // [buf][k][m]
    __shared__ uint32_t Bh[2][8][72],  Bl[2][8][72];    // [buf][k][n]

    int Kuse = KTRIM ? min(K, NH_ + bm + 128) : K;
    const int KT = (Kuse + 7) >> 3;

    // loaders
    const int am  = t >> 1;            // 0..127
    const int ak  = (t & 1) * 4;       // 0 or 4
    const int bkT = (t & 3) * 2;       // trans: k start
    const int bnT = t >> 2;            // trans: n (0..63)
    const int bkN = t >> 5;            // non-trans: k (0..7)
    const int bnN = (t & 31) * 2;      // non-trans: n start

    float a_st[4], b_st[2];

    auto load_tile = [&](int kt) {
        const int k0 = kt << 3;
#pragma unroll
        for (int j = 0; j < 4; j++) {
            int kk = k0 + ak + j;
            a_st[j] = (kk < Kuse) ? A[(size_t)(bm + am) * lda + kk] : 0.f;
        }
        if (TRANSB) {
#pragma unroll
            for (int j = 0; j < 2; j++) {
                int kk = k0 + bkT + j;
                b_st[j] = (kk < Kuse) ? Bm[(size_t)(bn + bnT) * ldb + kk] : 0.f;
            }
        } else {
            int kk = k0 + bkN;
#pragma unroll
            for (int j = 0; j < 2; j++) {
                b_st[j] = (kk < Kuse) ? Bm[(size_t)kk * ldb + bn + bnN + j] : 0.f;
            }
        }
    };
    auto store_tile = [&](int p) {
#pragma unroll
        for (int j = 0; j < 4; j++) {
            uint32_t hi, lo;
            split_tf32(a_st[j], hi, lo);
            Ah[p][ak + j][am] = hi;
            Al[p][ak + j][am] = lo;
        }
        if (TRANSB) {
#pragma unroll
            for (int j = 0; j < 2; j++) {
                uint32_t hi, lo;
                split_tf32(b_st[j], hi, lo);
                Bh[p][bkT + j][bnT] = hi;
                Bl[p][bkT + j][bnT] = lo;
            }
        } else {
#pragma unroll
            for (int j = 0; j < 2; j++) {
                uint32_t hi, lo;
                split_tf32(b_st[j], hi, lo);
                Bh[p][bkN][bnN + j] = hi;
                Bl[p][bkN][bnN + j] = lo;
            }
        }
    };

    float acc[2][4][4] = {};

    load_tile(0);
    store_tile(0);
    __syncthreads();
    int p = 0;
    for (int kt = 0; kt < KT; kt++) {
        if (kt + 1 < KT) load_tile(kt + 1);

        uint32_t ah[2][4], al[2][4], bh[4][2], bl[4][2];
#pragma unroll
        for (int mt = 0; mt < 2; mt++) {
            int mb = wm + mt * 16 + fg;
            ah[mt][0] = Ah[p][fc    ][mb];
            ah[mt][1] = Ah[p][fc    ][mb + 8];
            ah[mt][2] = Ah[p][fc + 4][mb];
            ah[mt][3] = Ah[p][fc + 4][mb + 8];
            al[mt][0] = Al[p][fc    ][mb];
            al[mt][1] = Al[p][fc    ][mb + 8];
            al[mt][2] = Al[p][fc + 4][mb];
            al[mt][3] = Al[p][fc + 4][mb + 8];
        }
#pragma unroll
        for (int nt = 0; nt < 4; nt++) {
            int nb = wn + nt * 8 + fg;
            bh[nt][0] = Bh[p][fc    ][nb];
            bh[nt][1] = Bh[p][fc + 4][nb];
            bl[nt][0] = Bl[p][fc    ][nb];
            bl[nt][1] = Bl[p][fc + 4][nb];
        }
#pragma unroll
        for (int mt = 0; mt < 2; mt++)
#pragma unroll
            for (int nt = 0; nt < 4; nt++) {
                mma_tf32(acc[mt][nt], ah[mt], bh[nt]);
                mma_tf32(acc[mt][nt], ah[mt], bl[nt]);
                mma_tf32(acc[mt][nt], al[mt], bh[nt]);
            }

        if (kt + 1 < KT) {
            store_tile(p ^ 1);
            __syncthreads();
            p ^= 1;
        }
    }

    // epilogue
#pragma unroll
    for (int mt = 0; mt < 2; mt++) {
#pragma unroll
        for (int nt = 0; nt < 4; nt++) {
            int n0 = bn + wn + nt * 8 + fc * 2;
#pragma unroll
            for (int half = 0; half < 2; half++) {
                int m = bm + wm + mt * 16 + fg + half * 8;
                float v0 = acc[mt][nt][half * 2];
                float v1 = acc[mt][nt][half * 2 + 1];
                if (MASKED) {
                    v0 = (n0     >= NH_ + m) ? -INFINITY : v0 * SCALE_;
                    v1 = (n0 + 1 >= NH_ + m) ? -INFINITY : v1 * SCALE_;
                } else {
                    if (bias) { v0 += bias[n0]; v1 += bias[n0 + 1]; }
                    if (RELU) { v0 = fmaxf(v0, 0.f); v1 = fmaxf(v1, 0.f); }
                    if (RESADD) {
                        float2 rr = *(const float2*)(res + (size_t)m * ldc + n0);
                        v0 += rr.x; v1 += rr.y;
                    }
                }
                *(float2*)(C + (size_t)m * ldc + n0) = make_float2(v0, v1);
            }
        }
    }
}

// ---------------- softmax over W (row-wise, handles -inf tail) ----------------
__global__ void softmax_rows() {
    const int row = blockIdx.x;  // B*H*NV
    float* p = g_scores + (size_t)row * W_;
    const int t = threadIdx.x;   // 128
    float vals[6];
    float m = -INFINITY;
#pragma unroll
    for (int i = 0; i < 6; i++) { vals[i] = p[t + i * 128]; m = fmaxf(m, vals[i]); }
    __shared__ float red[128];
    red[t] = m; __syncthreads();
    for (int s = 64; s > 0; s >>= 1) { if (t < s) red[t] = fmaxf(red[t], red[t + s]); __syncthreads(); }
    m = red[0];
    __syncthreads();
    float sum = 0.f;
#pragma unroll
    for (int i = 0; i < 6; i++) { vals[i] = __expf(vals[i] - m); sum += vals[i]; }
    red[t] = sum; __syncthreads();
    for (int s = 64; s > 0; s >>= 1) { if (t < s) red[t] += red[t + s]; __syncthreads(); }
    float inv = 1.f / red[0];
#pragma unroll
    for (int i = 0; i < 6; i++) p[t + i * 128] = vals[i] * inv;
}

// ---------------- layernorm: out = g * norm(base + delta) + beta ----------------
__global__ void ln_kernel(const float* __restrict__ base, const float* __restrict__ delta,
                          const float* __restrict__ gamma, const float* __restrict__ beta,
                          float* __restrict__ out) {
    const int row = blockIdx.x;  // B*NV
    const int t = threadIdx.x;   // 256
    const float* br = base + (size_t)row * HA_;
    float x0 = br[t];
    float x1 = br[t + 256];
    if (delta) {
        const float* dr = delta + (size_t)row * HA_;
        x0 += dr[t];
        x1 += dr[t + 256];
    }
    __shared__ float red[256];
    red[t] = x0 + x1; __syncthreads();
    for (int s = 128; s > 0; s >>= 1) { if (t < s) red[t] += red[t + s]; __syncthreads(); }
    float mean = red[0] * (1.f / HA_);
    __syncthreads();
    float d0 = x0 - mean, d1 = x1 - mean;
    red[t] = d0 * d0 + d1 * d1; __syncthreads();
    for (int s = 128; s > 0; s >>= 1) { if (t < s) red[t] += red[t + s]; __syncthreads(); }
    float inv = rsqrtf(red[0] * (1.f / HA_) + EPS_);
    out[(size_t)row * HA_ + t]       = gamma[t]       * (d0 * inv) + beta[t];
    out[(size_t)row * HA_ + t + 256] = gamma[t + 256] * (d1 * inv) + beta[t + 256];
}

// ---------------- final loss reduction (deterministic, one CTA per batch) ----------------
__global__ void loss_kernel(const float* __restrict__ pu, float* __restrict__ out) {
    const int b = blockIdx.x;
    const int t = threadIdx.x;           // 256 = 8 warps
    const int warp = t >> 5, lane = t & 31;
    const float LOG_R = logf((float)R_);
    float accum = 0.f;
    for (int v = 1 + warp; v < NV_; v += 8) {
        const float* lr = g_logits + ((size_t)(b * NV_ + v)) * R_;
        float lv[4];
        float m = -INFINITY;
#pragma unroll
        for (int i = 0; i < 4; i++) { lv[i] = lr[lane + i * 32]; m = fmaxf(m, lv[i]); }
#pragma unroll
        for (int o = 16; o > 0; o >>= 1) m = fmaxf(m, __shfl_xor_sync(0xffffffffu, m, o));
        float se = 0.f;
#pragma unroll
        for (int i = 0; i < 4; i++) se += expf(lv[i] - m);
#pragma unroll
        for (int o = 16; o > 0; o >>= 1) se += __shfl_xor_sync(0xffffffffu, se, o);
        if (lane == 0) {
            float lse = m + logf(se);
            int tgt = (int)floorf(pu[b * NV_ + v] * (float)R_);
            tgt = min(max(tgt, 0), R_ - 1);
            accum += lse - lr[tgt] - LOG_R;
        }
    }
    __shared__ float red[8];
    if (lane == 0) red[warp] = accum;
    __syncthreads();
    if (t == 0) {
        float s = 0.f;
#pragma unroll
        for (int i = 0; i < 8; i++) s += red[i];
        out[b] = s;
    }
}

// ---------------- host launch ----------------
static float* sym_addr(const void* sym) {
    void* p = nullptr;
    cudaGetSymbolAddress(&p, sym);
    return (float*)p;
}

extern "C" void kernel_launch(void* const* d_in, const int* in_sizes, int n_in,
                              void* d_out, int out_size) {
    (void)in_sizes; (void)n_in; (void)out_size;
    const float* hist  = (const float*)d_in[0];
    const float* hu    = (const float*)d_in[1];
    const float* pred  = (const float*)d_in[2];
    const float* pu    = (const float*)d_in[3];
    const float* ds_w  = (const float*)d_in[4];
    const float* ds_b  = (const float*)d_in[5];
    const float* key_w = (const float*)d_in[6];
    const float* key_b = (const float*)d_in[7];
    const float* val_w = (const float*)d_in[8];
    const float* val_b = (const float*)d_in[9];
    const float* ln1_g = (const float*)d_in[10];
    const float* ln1_b = (const float*)d_in[11];
    const float* ln2_g = (const float*)d_in[12];
    const float* ln2_b = (const float*)d_in[13];
    const float* ff_w1 = (const float*)d_in[14];
    const float* ff_b1 = (const float*)d_in[15];
    const float* ff_w2 = (const float*)d_in[16];
    const float* ff_b2 = (const float*)d_in[17];
    const float* ff_w3 = (const float*)d_in[18];
    const float* ff_b3 = (const float*)d_in[19];
    const float* de_w  = (const float*)d_in[20];
    const float* de_b  = (const float*)d_in[21];
    float* out = (float*)d_out;

    float* ki    = sym_addr(g_ki);
    float* kwT   = sym_addr(g_kwT);
    float* vwT   = sym_addr(g_vwT);
    float* att   = sym_addr(g_att);
    float* keys  = sym_addr(g_keys);
    float* vals  = sym_addr(g_vals);
    float* scr   = sym_addr(g_scores);
    float* res   = sym_addr(g_res);
    float* ff1   = sym_addr(g_ff1);
    float* ff2   = sym_addr(g_ff2);
    float* logit = sym_addr(g_logits);

    const int BNV = B_ * NV_;          // 4096
    const int BW  = B_ * W_;           // 12288

    // 1. inputs
    {
        int total = B_ * W_ * (D_ + 1);
        build_ki<<<(total + 255) / 256, 256>>>(hist, hu, pred, pu);
    }
    {
        int total = (D_ + 1) * GHA_;
        transpose_w<<<(total + 255) / 256, 256>>>(key_w, kwT);
        transpose_w<<<(total + 255) / 256, 256>>>(val_w, vwT);
    }
    // 2. att = pred @ ds_w + ds_b   [4096, 512] K=256
    gemm_tc<false, false, false, false, false><<<dim3(HA_ / 64, BNV / 128, 1), 256>>>(
        pred, ds_w, ds_b, nullptr, att, HA_, D_, D_, HA_, HA_,
        0, 0, 0, 0, 0, 0, 1);
    // 3. keys / vals = ki @ kwT + bias  [12288, 2048] K=257
    gemm_tc<false, false, false, false, false><<<dim3(GHA_ / 64, BW / 128, 1), 256>>>(
        ki, kwT, key_b, nullptr, keys, GHA_, D_ + 1, D_ + 1, GHA_, GHA_,
        0, 0, 0, 0, 0, 0, 1);
    gemm_tc<false, false, false, false, false><<<dim3(GHA_ / 64, BW / 128, 1), 256>>>(
        ki, vwT, val_b, nullptr, vals, GHA_, D_ + 1, D_ + 1, GHA_, GHA_,
        0, 0, 0, 0, 0, 0, 1);

    const long long sQ1  = (long long)NV_ * HA_;      // per-b stride of att
    const long long sKV1 = (long long)W_ * GHA_;      // per-b stride of keys/vals
    const long long sS   = (long long)NV_ * W_;       // per-(b,h) stride of scores
    const long long sO1  = (long long)NV_ * HA_;      // per-b stride of res/att

    // 4. layers
    for (int l = 0; l < L_; l++) {
        // scores[b,h,v,w] = mask(-inf) or scale * Q.K   (batched z = b*8+h)
        gemm_tc<true, true, false, false, false><<<dim3(W_ / 64, NV_ / 128, B_ * H_), 256>>>(
            att, keys + l * H_ * A_, nullptr, nullptr, scr,
            W_, A_, HA_, GHA_, W_,
            sQ1, (long long)A_, sKV1, (long long)A_, 8 * sS, sS, H_);
        softmax_rows<<<B_ * H_ * NV_, 128>>>();
        // res = att + P @ V  (batched, K trimmed to causal bound)
        gemm_tc<false, false, false, true, true><<<dim3(1, NV_ / 128, B_ * H_), 256>>>(
            scr, vals + l * H_ * A_, nullptr, att, res,
            A_, W_, W_, GHA_, HA_,
            8 * sS, sS, sKV1, (long long)A_, sO1, (long long)A_, H_);
        ln_kernel<<<BNV, 256>>>(res, nullptr, ln1_g + l * HA_, ln1_b + l * HA_, att);
        gemm_tc<false, false, true, false, false><<<dim3(M_ / 64, BNV / 128, 1), 256>>>(
            att, ff_w1 + (size_t)l * HA_ * M_, ff_b1 + l * M_, nullptr, ff1,
            M_, HA_, HA_, M_, M_, 0, 0, 0, 0, 0, 0, 1);
        gemm_tc<false, false, true, false, false><<<dim3(M_ / 64, BNV / 128, 1), 256>>>(
            ff1, ff_w2 + (size_t)l * M_ * M_, ff_b2 + l * M_, nullptr, ff2,
            M_, M_, M_, M_, M_, 0, 0, 0, 0, 0, 0, 1);
        gemm_tc<false, false, false, false, false><<<dim3(HA_ / 64, BNV / 128, 1), 256>>>(
            ff2, ff_w3 + (size_t)l * M_ * HA_, ff_b3 + l * HA_, nullptr, res,
            HA_, M_, M_, HA_, HA_, 0, 0, 0, 0, 0, 0, 1);
        ln_kernel<<<BNV, 256>>>(att, res, ln2_g + l * HA_, ln2_b + l * HA_, att);
    }
    // 5. logits + loss
    gemm_tc<false, false, false, false, false><<<dim3(R_ / 64, BNV / 128, 1), 256>>>(
        att, de_w, de_b, nullptr, logit, R_, HA_, HA_, R_, R_,
        0, 0, 0, 0, 0, 0, 1);
    loss_kernel<<<B_, 256>>>(pu, out);
}

// round 4
// speedup vs baseline: 1.2590x; 1.0785x over previous
#include <cuda_runtime.h>
#include <math.h>
#include <stdint.h>

// ---------------- problem constants ----------------
constexpr int B_  = 16;
constexpr int D_  = 256;
constexpr int NH_ = 512;
constexpr int NV_ = 256;
constexpr int W_  = 768;          // NH + NV
constexpr int L_  = 4;
constexpr int H_  = 8;
constexpr int A_  = 64;
constexpr int HA_ = 512;
constexpr int M_  = 512;
constexpr int R_  = 128;
constexpr int GHA_ = L_ * H_ * A_;   // 2048
constexpr float EPS_   = 1e-5f;
constexpr float SCALE_ = 0.125f;     // A^-0.5

// ---------------- device scratch (no allocs allowed) ----------------
__device__ float g_ki   [B_ * W_ * (D_ + 1)];
__device__ float g_kwT  [(D_ + 1) * GHA_];
__device__ float g_vwT  [(D_ + 1) * GHA_];
__device__ float g_att  [B_ * NV_ * HA_];
__device__ float g_keys [(size_t)B_ * W_ * GHA_];
__device__ float g_vals [(size_t)B_ * W_ * GHA_];
__device__ float g_scores[(size_t)B_ * H_ * NV_ * W_];
__device__ float g_res  [B_ * NV_ * HA_];
__device__ float g_ff1  [B_ * NV_ * M_];
__device__ float g_ff2  [B_ * NV_ * M_];
__device__ float g_logits[B_ * NV_ * R_];

// ---------------- build ki = [hist||u ; pred||u]  [B, W, 257] ----------------
__global__ void build_ki(const float* __restrict__ hist, const float* __restrict__ hu,
                         const float* __restrict__ pred, const float* __restrict__ pu) {
    int idx = blockIdx.x * blockDim.x + threadIdx.x;
    const int total = B_ * W_ * (D_ + 1);
    if (idx >= total) return;
    int d = idx % (D_ + 1);
    int w = (idx / (D_ + 1)) % W_;
    int b = idx / ((D_ + 1) * W_);
    float v;
    if (d < D_) {
        v = (w < NH_) ? hist[((size_t)(b * NH_ + w)) * D_ + d]
                      : pred[((size_t)(b * NV_ + (w - NH_))) * D_ + d];
    } else {
        v = (w < NH_) ? hu[b * NH_ + w] : pu[b * NV_ + (w - NH_)];
    }
    g_ki[idx] = v;
}

// key_w [L,H,257,A] -> [257, L*H*A]
__global__ void transpose_w(const float* __restrict__ src, float* __restrict__ dst) {
    int idx = blockIdx.x * blockDim.x + threadIdx.x;
    const int total = (D_ + 1) * GHA_;
    if (idx >= total) return;
    int c = idx % GHA_;
    int d = idx / GHA_;
    int g = c >> 6;        // l*H + h
    int a = c & 63;
    dst[idx] = src[((size_t)(g * (D_ + 1) + d)) * A_ + a];
}

// ---------------- tf32 helpers ----------------
__device__ __forceinline__ uint2 split_tf32(float x) {
    uint32_t hi, lo;
    asm("cvt.rna.tf32.f32 %0, %1;" : "=r"(hi) : "f"(x));
    float l = x - __uint_as_float(hi);
    asm("cvt.rna.tf32.f32 %0, %1;" : "=r"(lo) : "f"(l));
    return make_uint2(hi, lo);
}

__device__ __forceinline__ void mma_tf32(float (&d)[4], const uint32_t (&a)[4],
                                         const uint32_t (&b)[2]) {
    asm volatile(
        "mma.sync.aligned.m16n8k8.row.col.f32.tf32.tf32.f32 "
        "{%0,%1,%2,%3},{%4,%5,%6,%7},{%8,%9},{%0,%1,%2,%3};"
        : "+f"(d[0]), "+f"(d[1]), "+f"(d[2]), "+f"(d[3])
        : "r"(a[0]), "r"(a[1]), "r"(a[2]), "r"(a[3]), "r"(b[0]), "r"(b[1]));
}

// ======================================================================
// Tensor-core GEMM (3xTF32, fp32-equivalent accuracy).
// CTA tile 128 x BN (BN=128 or 64), 8 warps as 2(m) x 4(n),
// warp tile 64 x BN/4, m16n8k8, K-tile 8, double-buffered,
// hi/lo packed as uint2 in SMEM (LDS.64 fragment loads).
// Requires M % 128 == 0, N % BN == 0; K guarded.
// Batched via blockIdx.z with composite (z/Hdiv, z%Hdiv) strides.
// ======================================================================
template <int BN, bool TRANSB, bool MASKED, bool RELU, bool KTRIM, bool RESADD>
__global__ __launch_bounds__(256)
void gemm_tc(const float* __restrict__ A, const float* __restrict__ Bm,
             const float* __restrict__ bias, const float* __restrict__ resid,
             float* __restrict__ C,
             int N, int K, int lda, int ldb, int ldc,
             long long sA1, long long sA2, long long sB1, long long sB2,
             long long sC1, long long sC2, int Hdiv)
{
    constexpr int NT = BN / 32;        // n-tiles per warp (warp n = BN/4)
    const int z = blockIdx.z;
    const long long zq = z / Hdiv, zr = z % Hdiv;
    A  += zq * sA1 + zr * sA2;
    Bm += zq * sB1 + zr * sB2;
    const long long coff = zq * sC1 + zr * sC2;
    C += coff;
    const float* res = RESADD ? (resid + coff) : nullptr;

    const int bm = blockIdx.y * 128;
    const int bn = blockIdx.x * BN;
    const int t    = threadIdx.x;
    const int lane = t & 31;
    const int warp = t >> 5;
    const int wm = (warp >> 2) * 64;        // warp m offset (2 rows of warps)
    const int wn = (warp & 3) * (BN / 4);   // warp n offset (4 cols of warps)
    const int fc = lane & 3;
    const int fg = lane >> 2;

    if (MASKED && bn >= NH_ + bm + 128) {
        float2 ninf = make_float2(-INFINITY, -INFINITY);
#pragma unroll
        for (int mt = 0; mt < 4; mt++) {
            int m0 = bm + wm + mt * 16 + fg;
#pragma unroll
            for (int nt = 0; nt < NT; nt++) {
                int n0 = bn + wn + nt * 8 + fc * 2;
                *(float2*)(C + (size_t)m0 * ldc + n0) = ninf;
                *(float2*)(C + (size_t)(m0 + 8) * ldc + n0) = ninf;
            }
        }
        return;
    }

    __shared__ uint2 Ap[2][8][132];        // [buf][k][m] (hi,lo)
    __shared__ uint2 Bp[2][8][BN + 4];     // [buf][k][n]

    int Kuse = KTRIM ? min(K, NH_ + bm + 128) : K;
    const int KT = (Kuse + 7) >> 3;

    // loaders
    const int am  = t >> 1;                // 0..127
    const int ak  = (t & 1) * 4;           // 0 or 4
    const int bkN = t >> 5;                // non-trans: k (0..7)
    const int bnN = (t & 31) * (BN / 32);  // non-trans: n start
    const int bnT = t >> 1;                // trans: n (0..127)  [BN==128 only]
    const int bkT = (t & 1) * 4;           // trans: k start

    float a_st[4], b_st[4];

    auto load_tile = [&](int kt) {
        const int k0 = kt << 3;
#pragma unroll
        for (int j = 0; j < 4; j++) {
            int kk = k0 + ak + j;
            a_st[j] = (kk < Kuse) ? A[(size_t)(bm + am) * lda + kk] : 0.f;
        }
        if (TRANSB) {
#pragma unroll
            for (int j = 0; j < 4; j++) {
                int kk = k0 + bkT + j;
                b_st[j] = (kk < Kuse) ? Bm[(size_t)(bn + bnT) * ldb + kk] : 0.f;
            }
        } else {
            int kk = k0 + bkN;
#pragma unroll
            for (int j = 0; j < BN / 32; j++) {
                b_st[j] = (kk < Kuse) ? Bm[(size_t)kk * ldb + bn + bnN + j] : 0.f;
            }
        }
    };
    auto store_tile = [&](int p) {
#pragma unroll
        for (int j = 0; j < 4; j++)
            Ap[p][ak + j][am] = split_tf32(a_st[j]);
        if (TRANSB) {
#pragma unroll
            for (int j = 0; j < 4; j++)
                Bp[p][bkT + j][bnT] = split_tf32(b_st[j]);
        } else {
#pragma unroll
            for (int j = 0; j < BN / 32; j++)
                Bp[p][bkN][bnN + j] = split_tf32(b_st[j]);
        }
    };

    float acc[4][NT][4] = {};

    load_tile(0);
    store_tile(0);
    __syncthreads();
    int p = 0;
    for (int kt = 0; kt < KT; kt++) {
        if (kt + 1 < KT) load_tile(kt + 1);

        // B fragments (shared across all m-tiles)
        uint32_t bh[NT][2], bl[NT][2];
#pragma unroll
        for (int nt = 0; nt < NT; nt++) {
            int nb = wn + nt * 8 + fg;
            uint2 v0 = Bp[p][fc    ][nb];
            uint2 v1 = Bp[p][fc + 4][nb];
            bh[nt][0] = v0.x; bl[nt][0] = v0.y;
            bh[nt][1] = v1.x; bl[nt][1] = v1.y;
        }
#pragma unroll
        for (int mt = 0; mt < 4; mt++) {
            int mb = wm + mt * 16 + fg;
            uint32_t ah[4], al[4];
            uint2 v;
            v = Ap[p][fc    ][mb];     ah[0] = v.x; al[0] = v.y;
            v = Ap[p][fc    ][mb + 8]; ah[1] = v.x; al[1] = v.y;
            v = Ap[p][fc + 4][mb];     ah[2] = v.x; al[2] = v.y;
            v = Ap[p][fc + 4][mb + 8]; ah[3] = v.x; al[3] = v.y;
#pragma unroll
            for (int nt = 0; nt < NT; nt++) {
                mma_tf32(acc[mt][nt], ah, bh[nt]);
                mma_tf32(acc[mt][nt], ah, bl[nt]);
                mma_tf32(acc[mt][nt], al, bh[nt]);
            }
        }

        if (kt + 1 < KT) {
            store_tile(p ^ 1);
            __syncthreads();
            p ^= 1;
        }
    }

    // epilogue
#pragma unroll
    for (int mt = 0; mt < 4; mt++) {
#pragma unroll
        for (int nt = 0; nt < NT; nt++) {
            int n0 = bn + wn + nt * 8 + fc * 2;
#pragma unroll
            for (int half = 0; half < 2; half++) {
                int m = bm + wm + mt * 16 + fg + half * 8;
                float v0 = acc[mt][nt][half * 2];
                float v1 = acc[mt][nt][half * 2 + 1];
                if (MASKED) {
                    v0 = (n0     >= NH_ + m) ? -INFINITY : v0 * SCALE_;
                    v1 = (n0 + 1 >= NH_ + m) ? -INFINITY : v1 * SCALE_;
                } else {
                    if (bias) { v0 += bias[n0]; v1 += bias[n0 + 1]; }
                    if (RELU) { v0 = fmaxf(v0, 0.f); v1 = fmaxf(v1, 0.f); }
                    if (RESADD) {
                        float2 rr = *(const float2*)(res + (size_t)m * ldc + n0);
                        v0 += rr.x; v1 += rr.y;
                    }
                }
                *(float2*)(C + (size_t)m * ldc + n0) = make_float2(v0, v1);
            }
        }
    }
}

// ---------------- softmax over W (row-wise, handles -inf tail) ----------------
__global__ void softmax_rows() {
    const int row = blockIdx.x;  // B*H*NV
    float* p = g_scores + (size_t)row * W_;
    const int t = threadIdx.x;   // 128
    float vals[6];
    float m = -INFINITY;
#pragma unroll
    for (int i = 0; i < 6; i++) { vals[i] = p[t + i * 128]; m = fmaxf(m, vals[i]); }
    __shared__ float red[128];
    red[t] = m; __syncthreads();
    for (int s = 64; s > 0; s >>= 1) { if (t < s) red[t] = fmaxf(red[t], red[t + s]); __syncthreads(); }
    m = red[0];
    __syncthreads();
    float sum = 0.f;
#pragma unroll
    for (int i = 0; i < 6; i++) { vals[i] = __expf(vals[i] - m); sum += vals[i]; }
    red[t] = sum; __syncthreads();
    for (int s = 64; s > 0; s >>= 1) { if (t < s) red[t] += red[t + s]; __syncthreads(); }
    float inv = 1.f / red[0];
#pragma unroll
    for (int i = 0; i < 6; i++) p[t + i * 128] = vals[i] * inv;
}

// ---------------- layernorm: out = g * norm(base + delta) + beta ----------------
__global__ void ln_kernel(const float* __restrict__ base, const float* __restrict__ delta,
                          const float* __restrict__ gamma, const float* __restrict__ beta,
                          float* __restrict__ out) {
    const int row = blockIdx.x;  // B*NV
    const int t = threadIdx.x;   // 256
    const float* br = base + (size_t)row * HA_;
    float x0 = br[t];
    float x1 = br[t + 256];
    if (delta) {
        const float* dr = delta + (size_t)row * HA_;
        x0 += dr[t];
        x1 += dr[t + 256];
    }
    __shared__ float red[256];
    red[t] = x0 + x1; __syncthreads();
    for (int s = 128; s > 0; s >>= 1) { if (t < s) red[t] += red[t + s]; __syncthreads(); }
    float mean = red[0] * (1.f / HA_);
    __syncthreads();
    float d0 = x0 - mean, d1 = x1 - mean;
    red[t] = d0 * d0 + d1 * d1; __syncthreads();
    for (int s = 128; s > 0; s >>= 1) { if (t < s) red[t] += red[t + s]; __syncthreads(); }
    float inv = rsqrtf(red[0] * (1.f / HA_) + EPS_);
    out[(size_t)row * HA_ + t]       = gamma[t]       * (d0 * inv) + beta[t];
    out[(size_t)row * HA_ + t + 256] = gamma[t + 256] * (d1 * inv) + beta[t + 256];
}

// ---------------- final loss reduction (deterministic, one CTA per batch) ----------------
__global__ void loss_kernel(const float* __restrict__ pu, float* __restrict__ out) {
    const int b = blockIdx.x;
    const int t = threadIdx.x;           // 256 = 8 warps
    const int warp = t >> 5, lane = t & 31;
    const float LOG_R = logf((float)R_);
    float accum = 0.f;
    for (int v = 1 + warp; v < NV_; v += 8) {
        const float* lr = g_logits + ((size_t)(b * NV_ + v)) * R_;
        float lv[4];
        float m = -INFINITY;
#pragma unroll
        for (int i = 0; i < 4; i++) { lv[i] = lr[lane + i * 32]; m = fmaxf(m, lv[i]); }
#pragma unroll
        for (int o = 16; o > 0; o >>= 1) m = fmaxf(m, __shfl_xor_sync(0xffffffffu, m, o));
        float se = 0.f;
#pragma unroll
        for (int i = 0; i < 4; i++) se += expf(lv[i] - m);
#pragma unroll
        for (int o = 16; o > 0; o >>= 1) se += __shfl_xor_sync(0xffffffffu, se, o);
        if (lane == 0) {
            float lse = m + logf(se);
            int tgt = (int)floorf(pu[b * NV_ + v] * (float)R_);
            tgt = min(max(tgt, 0), R_ - 1);
            accum += lse - lr[tgt] - LOG_R;
        }
    }
    __shared__ float red[8];
    if (lane == 0) red[warp] = accum;
    __syncthreads();
    if (t == 0) {
        float s = 0.f;
#pragma unroll
        for (int i = 0; i < 8; i++) s += red[i];
        out[b] = s;
    }
}

// ---------------- host launch ----------------
static float* sym_addr(const void* sym) {
    void* p = nullptr;
    cudaGetSymbolAddress(&p, sym);
    return (float*)p;
}

extern "C" void kernel_launch(void* const* d_in, const int* in_sizes, int n_in,
                              void* d_out, int out_size) {
    (void)in_sizes; (void)n_in; (void)out_size;
    const float* hist  = (const float*)d_in[0];
    const float* hu    = (const float*)d_in[1];
    const float* pred  = (const float*)d_in[2];
    const float* pu    = (const float*)d_in[3];
    const float* ds_w  = (const float*)d_in[4];
    const float* ds_b  = (const float*)d_in[5];
    const float* key_w = (const float*)d_in[6];
    const float* key_b = (const float*)d_in[7];
    const float* val_w = (const float*)d_in[8];
    const float* val_b = (const float*)d_in[9];
    const float* ln1_g = (const float*)d_in[10];
    const float* ln1_b = (const float*)d_in[11];
    const float* ln2_g = (const float*)d_in[12];
    const float* ln2_b = (const float*)d_in[13];
    const float* ff_w1 = (const float*)d_in[14];
    const float* ff_b1 = (const float*)d_in[15];
    const float* ff_w2 = (const float*)d_in[16];
    const float* ff_b2 = (const float*)d_in[17];
    const float* ff_w3 = (const float*)d_in[18];
    const float* ff_b3 = (const float*)d_in[19];
    const float* de_w  = (const float*)d_in[20];
    const float* de_b  = (const float*)d_in[21];
    float* out = (float*)d_out;

    float* ki    = sym_addr(g_ki);
    float* kwT   = sym_addr(g_kwT);
    float* vwT   = sym_addr(g_vwT);
    float* att   = sym_addr(g_att);
    float* keys  = sym_addr(g_keys);
    float* vals  = sym_addr(g_vals);
    float* scr   = sym_addr(g_scores);
    float* res   = sym_addr(g_res);
    float* ff1   = sym_addr(g_ff1);
    float* ff2   = sym_addr(g_ff2);
    float* logit = sym_addr(g_logits);

    const int BNV = B_ * NV_;          // 4096
    const int BW  = B_ * W_;           // 12288

    // 1. inputs
    {
        int total = B_ * W_ * (D_ + 1);
        build_ki<<<(total + 255) / 256, 256>>>(hist, hu, pred, pu);
    }
    {
        int total = (D_ + 1) * GHA_;
        transpose_w<<<(total + 255) / 256, 256>>>(key_w, kwT);
        transpose_w<<<(total + 255) / 256, 256>>>(val_w, vwT);
    }
    // 2. att = pred @ ds_w + ds_b   [4096, 512] K=256
    gemm_tc<128, false, false, false, false, false><<<dim3(HA_ / 128, BNV / 128, 1), 256>>>(
        pred, ds_w, ds_b, nullptr, att, HA_, D_, D_, HA_, HA_,
        0, 0, 0, 0, 0, 0, 1);
    // 3. keys / vals = ki @ kwT + bias  [12288, 2048] K=257
    gemm_tc<128, false, false, false, false, false><<<dim3(GHA_ / 128, BW / 128, 1), 256>>>(
        ki, kwT, key_b, nullptr, keys, GHA_, D_ + 1, D_ + 1, GHA_, GHA_,
        0, 0, 0, 0, 0, 0, 1);
    gemm_tc<128, false, false, false, false, false><<<dim3(GHA_ / 128, BW / 128, 1), 256>>>(
        ki, vwT, val_b, nullptr, vals, GHA_, D_ + 1, D_ + 1, GHA_, GHA_,
        0, 0, 0, 0, 0, 0, 1);

    const long long sQ1  = (long long)NV_ * HA_;      // per-b stride of att
    const long long sKV1 = (long long)W_ * GHA_;      // per-b stride of keys/vals
    const long long sS   = (long long)NV_ * W_;       // per-(b,h) stride of scores
    const long long sO1  = (long long)NV_ * HA_;      // per-b stride of res/att

    // 4. layers
    for (int l = 0; l < L_; l++) {
        // scores[b,h,v,w] = mask(-inf) or scale * Q.K   (batched z = b*8+h)
        gemm_tc<128, true, true, false, false, false><<<dim3(W_ / 128, NV_ / 128, B_ * H_), 256>>>(
            att, keys + l * H_ * A_, nullptr, nullptr, scr,
            W_, A_, HA_, GHA_, W_,
            sQ1, (long long)A_, sKV1, (long long)A_, 8 * sS, sS, H_);
        softmax_rows<<<B_ * H_ * NV_, 128>>>();
        // res = att + P @ V  (batched, K trimmed to causal bound)
        gemm_tc<64, false, false, false, true, true><<<dim3(1, NV_ / 128, B_ * H_), 256>>>(
            scr, vals + l * H_ * A_, nullptr, att, res,
            A_, W_, W_, GHA_, HA_,
            8 * sS, sS, sKV1, (long long)A_, sO1, (long long)A_, H_);
        ln_kernel<<<BNV, 256>>>(res, nullptr, ln1_g + l * HA_, ln1_b + l * HA_, att);
        gemm_tc<128, false, false, true, false, false><<<dim3(M_ / 128, BNV / 128, 1), 256>>>(
            att, ff_w1 + (size_t)l * HA_ * M_, ff_b1 + l * M_, nullptr, ff1,
            M_, HA_, HA_, M_, M_, 0, 0, 0, 0, 0, 0, 1);
        gemm_tc<128, false, false, true, false, false><<<dim3(M_ / 128, BNV / 128, 1), 256>>>(
            ff1, ff_w2 + (size_t)l * M_ * M_, ff_b2 + l * M_, nullptr, ff2,
            M_, M_, M_, M_, M_, 0, 0, 0, 0, 0, 0, 1);
        gemm_tc<128, false, false, false, false, false><<<dim3(HA_ / 128, BNV / 128, 1), 256>>>(
            ff2, ff_w3 + (size_t)l * M_ * HA_, ff_b3 + l * HA_, nullptr, res,
            HA_, M_, M_, HA_, HA_, 0, 0, 0, 0, 0, 0, 1);
        ln_kernel<<<BNV, 256>>>(att, res, ln2_g + l * HA_, ln2_b + l * HA_, att);
    }
    // 5. logits + loss
    gemm_tc<128, false, false, false, false, false><<<dim3(1, BNV / 128, 1), 256>>>(
        att, de_w, de_b, nullptr, logit, R_, HA_, HA_, R_, R_,
        0, 0, 0, 0, 0, 0, 1);
    loss_kernel<<<B_, 256>>>(pu, out);
}

// round 5
// speedup vs baseline: 1.3516x; 1.0735x over previous
#include <cuda_runtime.h>
#include <math.h>
#include <stdint.h>

// ---------------- problem constants ----------------
constexpr int B_  = 16;
constexpr int D_  = 256;
constexpr int NH_ = 512;
constexpr int NV_ = 256;
constexpr int W_  = 768;          // NH + NV
constexpr int L_  = 4;
constexpr int H_  = 8;
constexpr int A_  = 64;
constexpr int HA_ = 512;
constexpr int M_  = 512;
constexpr int R_  = 128;
constexpr int GHA_ = L_ * H_ * A_;   // 2048
constexpr int KI_LD_ = 260;          // padded ki stride (16B-aligned rows)
constexpr float EPS_   = 1e-5f;
constexpr float SCALE_ = 0.125f;     // A^-0.5

// ---------------- device scratch (no allocs allowed) ----------------
__device__ float g_ki   [B_ * W_ * KI_LD_];
__device__ float g_kwT  [(D_ + 1) * GHA_];
__device__ float g_vwT  [(D_ + 1) * GHA_];
__device__ float g_att  [B_ * NV_ * HA_];
__device__ float g_keys [(size_t)B_ * W_ * GHA_];
__device__ float g_vals [(size_t)B_ * W_ * GHA_];
__device__ float g_scores[(size_t)B_ * H_ * NV_ * W_];
__device__ float g_res  [B_ * NV_ * HA_];
__device__ float g_ff1  [B_ * NV_ * M_];
__device__ float g_ff2  [B_ * NV_ * M_];
__device__ float g_logits[B_ * NV_ * R_];

// ---------------- build ki = [hist||u ; pred||u]  [B, W, 260(pad)] ----------------
__global__ void build_ki(const float* __restrict__ hist, const float* __restrict__ hu,
                         const float* __restrict__ pred, const float* __restrict__ pu) {
    int idx = blockIdx.x * blockDim.x + threadIdx.x;
    const int total = B_ * W_ * KI_LD_;
    if (idx >= total) return;
    int d = idx % KI_LD_;
    int w = (idx / KI_LD_) % W_;
    int b = idx / (KI_LD_ * W_);
    float v;
    if (d < D_) {
        v = (w < NH_) ? hist[((size_t)(b * NH_ + w)) * D_ + d]
                      : pred[((size_t)(b * NV_ + (w - NH_))) * D_ + d];
    } else if (d == D_) {
        v = (w < NH_) ? hu[b * NH_ + w] : pu[b * NV_ + (w - NH_)];
    } else {
        v = 0.f;
    }
    g_ki[idx] = v;
}

// key_w [L,H,257,A] -> [257, L*H*A]
__global__ void transpose_w(const float* __restrict__ src, float* __restrict__ dst) {
    int idx = blockIdx.x * blockDim.x + threadIdx.x;
    const int total = (D_ + 1) * GHA_;
    if (idx >= total) return;
    int c = idx % GHA_;
    int d = idx / GHA_;
    int g = c >> 6;        // l*H + h
    int a = c & 63;
    dst[idx] = src[((size_t)(g * (D_ + 1) + d)) * A_ + a];
}

// ---------------- tf32 helpers ----------------
__device__ __forceinline__ uint2 split_tf32(float x) {
    uint32_t hi, lo;
    asm("cvt.rna.tf32.f32 %0, %1;" : "=r"(hi) : "f"(x));
    float l = x - __uint_as_float(hi);
    asm("cvt.rna.tf32.f32 %0, %1;" : "=r"(lo) : "f"(l));
    return make_uint2(hi, lo);
}

__device__ __forceinline__ void mma_tf32(float (&d)[4], const uint32_t (&a)[4],
                                         const uint32_t (&b)[2]) {
    asm volatile(
        "mma.sync.aligned.m16n8k8.row.col.f32.tf32.tf32.f32 "
        "{%0,%1,%2,%3},{%4,%5,%6,%7},{%8,%9},{%0,%1,%2,%3};"
        : "+f"(d[0]), "+f"(d[1]), "+f"(d[2]), "+f"(d[3])
        : "r"(a[0]), "r"(a[1]), "r"(a[2]), "r"(a[3]), "r"(b[0]), "r"(b[1]));
}

// ======================================================================
// Tensor-core GEMM (3xTF32, fp32-equivalent accuracy).
// CTA: 128 threads, tile 128(m) x 64(n); 4 warps as 2(m) x 2(n);
// warp tile 64x32 = 4 mtiles x 4 ntiles of m16n8k8; K-tile 8;
// double-buffered SMEM of hi/lo-packed uint2 (LDS.64 fragments);
// float4 global loads (scalar-guarded K tail). 4 CTAs/SM.
// Requires: M % 128 == 0, N % 64 == 0, A/B rows 16B-aligned.
// Batched via blockIdx.z with composite (z/Hdiv, z%Hdiv) strides.
// ======================================================================
template <bool TRANSB, bool MASKED, bool RELU, bool KTRIM, bool RESADD>
__global__ __launch_bounds__(128, 4)
void gemm_tc(const float* __restrict__ A, const float* __restrict__ Bm,
             const float* __restrict__ bias, const float* __restrict__ resid,
             float* __restrict__ C,
             int N, int K, int lda, int ldb, int ldc,
             long long sA1, long long sA2, long long sB1, long long sB2,
             long long sC1, long long sC2, int Hdiv)
{
    const int z = blockIdx.z;
    const long long zq = z / Hdiv, zr = z % Hdiv;
    A  += zq * sA1 + zr * sA2;
    Bm += zq * sB1 + zr * sB2;
    const long long coff = zq * sC1 + zr * sC2;
    C += coff;
    const float* res = RESADD ? (resid + coff) : nullptr;

    const int bm = blockIdx.y * 128;
    const int bn = blockIdx.x * 64;
    const int t    = threadIdx.x;
    const int lane = t & 31;
    const int warp = t >> 5;
    const int wm = (warp >> 1) * 64;     // warp m offset
    const int wn = (warp & 1) * 32;      // warp n offset
    const int fc = lane & 3;
    const int fg = lane >> 2;

    if (MASKED && bn >= NH_ + bm + 128) {
        float2 ninf = make_float2(-INFINITY, -INFINITY);
#pragma unroll
        for (int mt = 0; mt < 4; mt++) {
            int m0 = bm + wm + mt * 16 + fg;
#pragma unroll
            for (int nt = 0; nt < 4; nt++) {
                int n0 = bn + wn + nt * 8 + fc * 2;
                *(float2*)(C + (size_t)m0 * ldc + n0) = ninf;
                *(float2*)(C + (size_t)(m0 + 8) * ldc + n0) = ninf;
            }
        }
        return;
    }

    __shared__ uint2 Ap[2][8][132];      // [buf][k][m]
    __shared__ uint2 Bp[2][8][68];       // [buf][k][n]

    int Kuse = KTRIM ? min(K, NH_ + bm + 128) : K;
    const int KT = (Kuse + 7) >> 3;

    // A loader: one row per thread, 8 consecutive k (two float4)
    const int am = t;
    // B non-trans: row bk (0..7), 4 consecutive n
    const int bkN = t >> 4, bnN = (t & 15) * 4;
    // B trans: row n (0..63), 4 consecutive k
    const int bnT = t >> 1, bkT = (t & 1) * 4;

    float a_st[8], b_st[4];

    auto load_tile = [&](int kt) {
        const int k0 = kt << 3;
        const float* arow = A + (size_t)(bm + am) * lda + k0;
        if (k0 + 8 <= Kuse) {
            float4 v0 = *(const float4*)(arow);
            float4 v1 = *(const float4*)(arow + 4);
            a_st[0] = v0.x; a_st[1] = v0.y; a_st[2] = v0.z; a_st[3] = v0.w;
            a_st[4] = v1.x; a_st[5] = v1.y; a_st[6] = v1.z; a_st[7] = v1.w;
        } else {
#pragma unroll
            for (int j = 0; j < 8; j++)
                a_st[j] = (k0 + j < Kuse) ? arow[j] : 0.f;
        }
        if (TRANSB) {
            const float* brow = Bm + (size_t)(bn + bnT) * ldb + k0 + bkT;
            if (k0 + 8 <= Kuse) {
                float4 v = *(const float4*)(brow);
                b_st[0] = v.x; b_st[1] = v.y; b_st[2] = v.z; b_st[3] = v.w;
            } else {
#pragma unroll
                for (int j = 0; j < 4; j++)
                    b_st[j] = (k0 + bkT + j < Kuse) ? brow[j] : 0.f;
            }
        } else {
            const float* brow = Bm + (size_t)(k0 + bkN) * ldb + bn + bnN;
            if (k0 + bkN < Kuse) {
                float4 v = *(const float4*)(brow);
                b_st[0] = v.x; b_st[1] = v.y; b_st[2] = v.z; b_st[3] = v.w;
            } else {
                b_st[0] = b_st[1] = b_st[2] = b_st[3] = 0.f;
            }
        }
    };
    auto store_tile = [&](int p) {
#pragma unroll
        for (int j = 0; j < 8; j++)
            Ap[p][j][am] = split_tf32(a_st[j]);
        if (TRANSB) {
#pragma unroll
            for (int j = 0; j < 4; j++)
                Bp[p][bkT + j][bnT] = split_tf32(b_st[j]);
        } else {
#pragma unroll
            for (int j = 0; j < 4; j++)
                Bp[p][bkN][bnN + j] = split_tf32(b_st[j]);
        }
    };

    float acc[4][4][4] = {};

    load_tile(0);
    store_tile(0);
    __syncthreads();
    int p = 0;
    for (int kt = 0; kt < KT; kt++) {
        if (kt + 1 < KT) load_tile(kt + 1);

        // B fragments (shared across all m-tiles)
        uint32_t bh[4][2], bl[4][2];
#pragma unroll
        for (int nt = 0; nt < 4; nt++) {
            int nb = wn + nt * 8 + fg;
            uint2 v0 = Bp[p][fc    ][nb];
            uint2 v1 = Bp[p][fc + 4][nb];
            bh[nt][0] = v0.x; bl[nt][0] = v0.y;
            bh[nt][1] = v1.x; bl[nt][1] = v1.y;
        }
#pragma unroll
        for (int mt = 0; mt < 4; mt++) {
            int mb = wm + mt * 16 + fg;
            uint32_t ah[4], al[4];
            uint2 v;
            v = Ap[p][fc    ][mb];     ah[0] = v.x; al[0] = v.y;
            v = Ap[p][fc    ][mb + 8]; ah[1] = v.x; al[1] = v.y;
            v = Ap[p][fc + 4][mb];     ah[2] = v.x; al[2] = v.y;
            v = Ap[p][fc + 4][mb + 8]; ah[3] = v.x; al[3] = v.y;
#pragma unroll
            for (int nt = 0; nt < 4; nt++) {
                mma_tf32(acc[mt][nt], ah, bh[nt]);
                mma_tf32(acc[mt][nt], ah, bl[nt]);
                mma_tf32(acc[mt][nt], al, bh[nt]);
            }
        }

        if (kt + 1 < KT) {
            store_tile(p ^ 1);
            __syncthreads();
            p ^= 1;
        }
    }

    // epilogue
#pragma unroll
    for (int mt = 0; mt < 4; mt++) {
#pragma unroll
        for (int nt = 0; nt < 4; nt++) {
            int n0 = bn + wn + nt * 8 + fc * 2;
#pragma unroll
            for (int half = 0; half < 2; half++) {
                int m = bm + wm + mt * 16 + fg + half * 8;
                float v0 = acc[mt][nt][half * 2];
                float v1 = acc[mt][nt][half * 2 + 1];
                if (MASKED) {
                    v0 = (n0     >= NH_ + m) ? -INFINITY : v0 * SCALE_;
                    v1 = (n0 + 1 >= NH_ + m) ? -INFINITY : v1 * SCALE_;
                } else {
                    if (bias) { v0 += bias[n0]; v1 += bias[n0 + 1]; }
                    if (RELU) { v0 = fmaxf(v0, 0.f); v1 = fmaxf(v1, 0.f); }
                    if (RESADD) {
                        float2 rr = *(const float2*)(res + (size_t)m * ldc + n0);
                        v0 += rr.x; v1 += rr.y;
                    }
                }
                *(float2*)(C + (size_t)m * ldc + n0) = make_float2(v0, v1);
            }
        }
    }
}

// ---------------- softmax over W (row-wise, handles -inf tail) ----------------
__global__ void softmax_rows() {
    const int row = blockIdx.x;  // B*H*NV
    float* p = g_scores + (size_t)row * W_;
    const int t = threadIdx.x;   // 128
    float vals[6];
    float m = -INFINITY;
#pragma unroll
    for (int i = 0; i < 6; i++) { vals[i] = p[t + i * 128]; m = fmaxf(m, vals[i]); }
    __shared__ float red[128];
    red[t] = m; __syncthreads();
    for (int s = 64; s > 0; s >>= 1) { if (t < s) red[t] = fmaxf(red[t], red[t + s]); __syncthreads(); }
    m = red[0];
    __syncthreads();
    float sum = 0.f;
#pragma unroll
    for (int i = 0; i < 6; i++) { vals[i] = __expf(vals[i] - m); sum += vals[i]; }
    red[t] = sum; __syncthreads();
    for (int s = 64; s > 0; s >>= 1) { if (t < s) red[t] += red[t + s]; __syncthreads(); }
    float inv = 1.f / red[0];
#pragma unroll
    for (int i = 0; i < 6; i++) p[t + i * 128] = vals[i] * inv;
}

// ---------------- layernorm: out = g * norm(base + delta) + beta ----------------
__global__ void ln_kernel(const float* __restrict__ base, const float* __restrict__ delta,
                          const float* __restrict__ gamma, const float* __restrict__ beta,
                          float* __restrict__ out) {
    const int row = blockIdx.x;  // B*NV
    const int t = threadIdx.x;   // 256
    const float* br = base + (size_t)row * HA_;
    float x0 = br[t];
    float x1 = br[t + 256];
    if (delta) {
        const float* dr = delta + (size_t)row * HA_;
        x0 += dr[t];
        x1 += dr[t + 256];
    }
    __shared__ float red[256];
    red[t] = x0 + x1; __syncthreads();
    for (int s = 128; s > 0; s >>= 1) { if (t < s) red[t] += red[t + s]; __syncthreads(); }
    float mean = red[0] * (1.f / HA_);
    __syncthreads();
    float d0 = x0 - mean, d1 = x1 - mean;
    red[t] = d0 * d0 + d1 * d1; __syncthreads();
    for (int s = 128; s > 0; s >>= 1) { if (t < s) red[t] += red[t + s]; __syncthreads(); }
    float inv = rsqrtf(red[0] * (1.f / HA_) + EPS_);
    out[(size_t)row * HA_ + t]       = gamma[t]       * (d0 * inv) + beta[t];
    out[(size_t)row * HA_ + t + 256] = gamma[t + 256] * (d1 * inv) + beta[t + 256];
}

// ---------------- final loss reduction (deterministic, one CTA per batch) ----------------
__global__ void loss_kernel(const float* __restrict__ pu, float* __restrict__ out) {
    const int b = blockIdx.x;
    const int t = threadIdx.x;           // 256 = 8 warps
    const int warp = t >> 5, lane = t & 31;
    const float LOG_R = logf((float)R_);
    float accum = 0.f;
    for (int v = 1 + warp; v < NV_; v += 8) {
        const float* lr = g_logits + ((size_t)(b * NV_ + v)) * R_;
        float lv[4];
        float m = -INFINITY;
#pragma unroll
        for (int i = 0; i < 4; i++) { lv[i] = lr[lane + i * 32]; m = fmaxf(m, lv[i]); }
#pragma unroll
        for (int o = 16; o > 0; o >>= 1) m = fmaxf(m, __shfl_xor_sync(0xffffffffu, m, o));
        float se = 0.f;
#pragma unroll
        for (int i = 0; i < 4; i++) se += expf(lv[i] - m);
#pragma unroll
        for (int o = 16; o > 0; o >>= 1) se += __shfl_xor_sync(0xffffffffu, se, o);
        if (lane == 0) {
            float lse = m + logf(se);
            int tgt = (int)floorf(pu[b * NV_ + v] * (float)R_);
            tgt = min(max(tgt, 0), R_ - 1);
            accum += lse - lr[tgt] - LOG_R;
        }
    }
    __shared__ float red[8];
    if (lane == 0) red[warp] = accum;
    __syncthreads();
    if (t == 0) {
        float s = 0.f;
#pragma unroll
        for (int i = 0; i < 8; i++) s += red[i];
        out[b] = s;
    }
}

// ---------------- host launch ----------------
static float* sym_addr(const void* sym) {
    void* p = nullptr;
    cudaGetSymbolAddress(&p, sym);
    return (float*)p;
}

extern "C" void kernel_launch(void* const* d_in, const int* in_sizes, int n_in,
                              void* d_out, int out_size) {
    (void)in_sizes; (void)n_in; (void)out_size;
    const float* hist  = (const float*)d_in[0];
    const float* hu    = (const float*)d_in[1];
    const float* pred  = (const float*)d_in[2];
    const float* pu    = (const float*)d_in[3];
    const float* ds_w  = (const float*)d_in[4];
    const float* ds_b  = (const float*)d_in[5];
    const float* key_w = (const float*)d_in[6];
    const float* key_b = (const float*)d_in[7];
    const float* val_w = (const float*)d_in[8];
    const float* val_b = (const float*)d_in[9];
    const float* ln1_g = (const float*)d_in[10];
    const float* ln1_b = (const float*)d_in[11];
    const float* ln2_g = (const float*)d_in[12];
    const float* ln2_b = (const float*)d_in[13];
    const float* ff_w1 = (const float*)d_in[14];
    const float* ff_b1 = (const float*)d_in[15];
    const float* ff_w2 = (const float*)d_in[16];
    const float* ff_b2 = (const float*)d_in[17];
    const float* ff_w3 = (const float*)d_in[18];
    const float* ff_b3 = (const float*)d_in[19];
    const float* de_w  = (const float*)d_in[20];
    const float* de_b  = (const float*)d_in[21];
    float* out = (float*)d_out;

    float* ki    = sym_addr(g_ki);
    float* kwT   = sym_addr(g_kwT);
    float* vwT   = sym_addr(g_vwT);
    float* att   = sym_addr(g_att);
    float* keys  = sym_addr(g_keys);
    float* vals  = sym_addr(g_vals);
    float* scr   = sym_addr(g_scores);
    float* res   = sym_addr(g_res);
    float* ff1   = sym_addr(g_ff1);
    float* ff2   = sym_addr(g_ff2);
    float* logit = sym_addr(g_logits);

    const int BNV = B_ * NV_;          // 4096
    const int BW  = B_ * W_;           // 12288

    // 1. inputs
    {
        int total = B_ * W_ * KI_LD_;
        build_ki<<<(total + 255) / 256, 256>>>(hist, hu, pred, pu);
    }
    {
        int total = (D_ + 1) * GHA_;
        transpose_w<<<(total + 255) / 256, 256>>>(key_w, kwT);
        transpose_w<<<(total + 255) / 256, 256>>>(val_w, vwT);
    }
    // 2. att = pred @ ds_w + ds_b   [4096, 512] K=256
    gemm_tc<false, false, false, false, false><<<dim3(HA_ / 64, BNV / 128, 1), 128>>>(
        pred, ds_w, ds_b, nullptr, att, HA_, D_, D_, HA_, HA_,
        0, 0, 0, 0, 0, 0, 1);
    // 3. keys / vals = ki @ kwT + bias  [12288, 2048] K=257
    gemm_tc<false, false, false, false, false><<<dim3(GHA_ / 64, BW / 128, 1), 128>>>(
        ki, kwT, key_b, nullptr, keys, GHA_, D_ + 1, KI_LD_, GHA_, GHA_,
        0, 0, 0, 0, 0, 0, 1);
    gemm_tc<false, false, false, false, false><<<dim3(GHA_ / 64, BW / 128, 1), 128>>>(
        ki, vwT, val_b, nullptr, vals, GHA_, D_ + 1, KI_LD_, GHA_, GHA_,
        0, 0, 0, 0, 0, 0, 1);

    const long long sQ1  = (long long)NV_ * HA_;      // per-b stride of att
    const long long sKV1 = (long long)W_ * GHA_;      // per-b stride of keys/vals
    const long long sS   = (long long)NV_ * W_;       // per-(b,h) stride of scores
    const long long sO1  = (long long)NV_ * HA_;      // per-b stride of res/att

    // 4. layers
    for (int l = 0; l < L_; l++) {
        // scores[b,h,v,w] = mask(-inf) or scale * Q.K   (batched z = b*8+h)
        gemm_tc<true, true, false, false, false><<<dim3(W_ / 64, NV_ / 128, B_ * H_), 128>>>(
            att, keys + l * H_ * A_, nullptr, nullptr, scr,
            W_, A_, HA_, GHA_, W_,
            sQ1, (long long)A_, sKV1, (long long)A_, 8 * sS, sS, H_);
        softmax_rows<<<B_ * H_ * NV_, 128>>>();
        // res = att + P @ V  (batched, K trimmed to causal bound)
        gemm_tc<false, false, false, true, true><<<dim3(1, NV_ / 128, B_ * H_), 128>>>(
            scr, vals + l * H_ * A_, nullptr, att, res,
            A_, W_, W_, GHA_, HA_,
            8 * sS, sS, sKV1, (long long)A_, sO1, (long long)A_, H_);
        ln_kernel<<<BNV, 256>>>(res, nullptr, ln1_g + l * HA_, ln1_b + l * HA_, att);
        gemm_tc<false, false, true, false, false><<<dim3(M_ / 64, BNV / 128, 1), 128>>>(
            att, ff_w1 + (size_t)l * HA_ * M_, ff_b1 + l * M_, nullptr, ff1,
            M_, HA_, HA_, M_, M_, 0, 0, 0, 0, 0, 0, 1);
        gemm_tc<false, false, true, false, false><<<dim3(M_ / 64, BNV / 128, 1), 128>>>(
            ff1, ff_w2 + (size_t)l * M_ * M_, ff_b2 + l * M_, nullptr, ff2,
            M_, M_, M_, M_, M_, 0, 0, 0, 0, 0, 0, 1);
        gemm_tc<false, false, false, false, false><<<dim3(HA_ / 64, BNV / 128, 1), 128>>>(
            ff2, ff_w3 + (size_t)l * M_ * HA_, ff_b3 + l * HA_, nullptr, res,
            HA_, M_, M_, HA_, HA_, 0, 0, 0, 0, 0, 0, 1);
        ln_kernel<<<BNV, 256>>>(att, res, ln2_g + l * HA_, ln2_b + l * HA_, att);
    }
    // 5. logits + loss
    gemm_tc<false, false, false, false, false><<<dim3(R_ / 64, BNV / 128, 1), 128>>>(
        att, de_w, de_b, nullptr, logit, R_, HA_, HA_, R_, R_,
        0, 0, 0, 0, 0, 0, 1);
    loss_kernel<<<B_, 256>>>(pu, out);
}

// round 6
// speedup vs baseline: 1.4207x; 1.0511x over previous
#include <cuda_runtime.h>
#include <math.h>
#include <stdint.h>

// ---------------- problem constants ----------------
constexpr int B_  = 16;
constexpr int D_  = 256;
constexpr int NH_ = 512;
constexpr int NV_ = 256;
constexpr int W_  = 768;          // NH + NV
constexpr int L_  = 4;
constexpr int H_  = 8;
constexpr int A_  = 64;
constexpr int HA_ = 512;
constexpr int M_  = 512;
constexpr int R_  = 128;
constexpr int GHA_ = L_ * H_ * A_;   // 2048
constexpr int KI_LD_ = 260;          // padded ki stride (16B-aligned rows)
constexpr float EPS_   = 1e-5f;
constexpr float SCALE_ = 0.125f;     // A^-0.5

// ---------------- device scratch (no allocs allowed) ----------------
__device__ float g_ki   [B_ * W_ * KI_LD_];
__device__ float g_kwT  [(D_ + 1) * GHA_];
__device__ float g_vwT  [(D_ + 1) * GHA_];
__device__ float g_att  [B_ * NV_ * HA_];
__device__ float g_keys [(size_t)B_ * W_ * GHA_];
__device__ float g_vals [(size_t)B_ * W_ * GHA_];
__device__ float g_scores[(size_t)B_ * H_ * NV_ * W_];
__device__ float g_res  [B_ * NV_ * HA_];
__device__ float g_ff1  [B_ * NV_ * M_];
__device__ float g_ff2  [B_ * NV_ * M_];
__device__ float g_logits[B_ * NV_ * R_];

// ---------------- build ki = [hist||u ; pred||u]  [B, W, 260(pad)] ----------------
__global__ void build_ki(const float* __restrict__ hist, const float* __restrict__ hu,
                         const float* __restrict__ pred, const float* __restrict__ pu) {
    int idx = blockIdx.x * blockDim.x + threadIdx.x;
    const int total = B_ * W_ * KI_LD_;
    if (idx >= total) return;
    int d = idx % KI_LD_;
    int w = (idx / KI_LD_) % W_;
    int b = idx / (KI_LD_ * W_);
    float v;
    if (d < D_) {
        v = (w < NH_) ? hist[((size_t)(b * NH_ + w)) * D_ + d]
                      : pred[((size_t)(b * NV_ + (w - NH_))) * D_ + d];
    } else if (d == D_) {
        v = (w < NH_) ? hu[b * NH_ + w] : pu[b * NV_ + (w - NH_)];
    } else {
        v = 0.f;
    }
    g_ki[idx] = v;
}

// key_w [L,H,257,A] -> [257, L*H*A]
__global__ void transpose_w(const float* __restrict__ src, float* __restrict__ dst) {
    int idx = blockIdx.x * blockDim.x + threadIdx.x;
    const int total = (D_ + 1) * GHA_;
    if (idx >= total) return;
    int c = idx % GHA_;
    int d = idx / GHA_;
    int g = c >> 6;        // l*H + h
    int a = c & 63;
    dst[idx] = src[((size_t)(g * (D_ + 1) + d)) * A_ + a];
}

// ---------------- tf32 helpers ----------------
__device__ __forceinline__ uint2 split_tf32(float x) {
    uint32_t hi, lo;
    asm("cvt.rna.tf32.f32 %0, %1;" : "=r"(hi) : "f"(x));
    float l = x - __uint_as_float(hi);
    asm("cvt.rna.tf32.f32 %0, %1;" : "=r"(lo) : "f"(l));
    return make_uint2(hi, lo);
}

__device__ __forceinline__ void mma_tf32(float (&d)[4], const uint32_t (&a)[4],
                                         const uint32_t (&b)[2]) {
    asm volatile(
        "mma.sync.aligned.m16n8k8.row.col.f32.tf32.tf32.f32 "
        "{%0,%1,%2,%3},{%4,%5,%6,%7},{%8,%9},{%0,%1,%2,%3};"
        : "+f"(d[0]), "+f"(d[1]), "+f"(d[2]), "+f"(d[3])
        : "r"(a[0]), "r"(a[1]), "r"(a[2]), "r"(a[3]), "r"(b[0]), "r"(b[1]));
}

// ======================================================================
// Tensor-core GEMM (3xTF32, fp32-equivalent accuracy).
// CTA: 128 threads, tile BM(m) x 64(n); 4 warps as 2(m) x 2(n);
// warp tile (BM/2)x32 = MT mtiles x 4 ntiles of m16n8k8; K-tile KTILE;
// double-buffered SMEM of hi/lo-packed uint2 (LDS.64 fragments);
// float4 global loads (scalar-guarded K tail).
//   BM=128, KTILE=8  : big-grid GEMMs (keys/vals/scores)
//   BM=64,  KTILE=16 : grid-starved GEMMs (FFN/ds/PV/logits) -> 2x CTAs,
//                      half the barriers, 16 warps/SM.
// Batched via blockIdx.z with composite (z/Hdiv, z%Hdiv) strides.
// ======================================================================
template <int BM, int KTILE, bool TRANSB, bool MASKED, bool RELU, bool KTRIM, bool RESADD>
__global__ __launch_bounds__(128, 4)
void gemm_tc(const float* __restrict__ A, const float* __restrict__ Bm,
             const float* __restrict__ bias, const float* __restrict__ resid,
             float* __restrict__ C,
             int N, int K, int lda, int ldb, int ldc,
             long long sA1, long long sA2, long long sB1, long long sB2,
             long long sC1, long long sC2, int Hdiv)
{
    constexpr int MT  = BM / 32;        // mtiles per warp
    constexpr int NPT = KTILE / 2;      // B floats per thread (non-trans)
    constexpr int TPR = KTILE / 8;      // threads per A row
    const int z = blockIdx.z;
    const long long zq = z / Hdiv, zr = z % Hdiv;
    A  += zq * sA1 + zr * sA2;
    Bm += zq * sB1 + zr * sB2;
    const long long coff = zq * sC1 + zr * sC2;
    C += coff;
    const float* res = RESADD ? (resid + coff) : nullptr;

    const int bm = blockIdx.y * BM;
    const int bn = blockIdx.x * 64;
    const int t    = threadIdx.x;
    const int lane = t & 31;
    const int warp = t >> 5;
    const int wm = (warp >> 1) * (BM / 2);   // warp m offset
    const int wn = (warp & 1) * 32;          // warp n offset
    const int fc = lane & 3;
    const int fg = lane >> 2;

    if (MASKED && bn >= NH_ + bm + BM) {
        float2 ninf = make_float2(-INFINITY, -INFINITY);
#pragma unroll
        for (int mt = 0; mt < MT; mt++) {
            int m0 = bm + wm + mt * 16 + fg;
#pragma unroll
            for (int nt = 0; nt < 4; nt++) {
                int n0 = bn + wn + nt * 8 + fc * 2;
                *(float2*)(C + (size_t)m0 * ldc + n0) = ninf;
                *(float2*)(C + (size_t)(m0 + 8) * ldc + n0) = ninf;
            }
        }
        return;
    }

    __shared__ uint2 Ap[2][KTILE][BM + 4];   // [buf][k][m]
    __shared__ uint2 Bp[2][KTILE][68];       // [buf][k][n]

    int Kuse = KTRIM ? min(K, NH_ + bm + BM) : K;
    const int KT = (Kuse + KTILE - 1) / KTILE;

    // A loader: row am, 8 consecutive k starting at ak
    const int am = t / TPR;
    const int ak = (t % TPR) * 8;
    // B non-trans: row bkN, NPT consecutive n
    const int bkN = t / (64 / NPT), bnN = (t % (64 / NPT)) * NPT;
    // B trans: row n, KTILE/2 consecutive k
    const int bnT = t >> 1, bkT = (t & 1) * (KTILE / 2);

    float a_st[8], b_st[NPT];

    auto load_tile = [&](int kt) {
        const int k0 = kt * KTILE;
        const float* arow = A + (size_t)(bm + am) * lda + k0 + ak;
        if (k0 + ak + 8 <= Kuse) {
            float4 v0 = *(const float4*)(arow);
            float4 v1 = *(const float4*)(arow + 4);
            a_st[0] = v0.x; a_st[1] = v0.y; a_st[2] = v0.z; a_st[3] = v0.w;
            a_st[4] = v1.x; a_st[5] = v1.y; a_st[6] = v1.z; a_st[7] = v1.w;
        } else {
#pragma unroll
            for (int j = 0; j < 8; j++)
                a_st[j] = (k0 + ak + j < Kuse) ? arow[j] : 0.f;
        }
        if (TRANSB) {
            const float* brow = Bm + (size_t)(bn + bnT) * ldb + k0 + bkT;
            if (k0 + bkT + KTILE / 2 <= Kuse) {
#pragma unroll
                for (int q = 0; q < KTILE / 8; q++) {
                    float4 v = *(const float4*)(brow + q * 4);
                    b_st[q * 4 + 0] = v.x; b_st[q * 4 + 1] = v.y;
                    b_st[q * 4 + 2] = v.z; b_st[q * 4 + 3] = v.w;
                }
            } else {
#pragma unroll
                for (int j = 0; j < KTILE / 2; j++)
                    b_st[j] = (k0 + bkT + j < Kuse) ? brow[j] : 0.f;
            }
        } else {
            const float* brow = Bm + (size_t)(k0 + bkN) * ldb + bn + bnN;
            if (k0 + bkN < Kuse) {
#pragma unroll
                for (int q = 0; q < NPT / 4; q++) {
                    float4 v = *(const float4*)(brow + q * 4);
                    b_st[q * 4 + 0] = v.x; b_st[q * 4 + 1] = v.y;
                    b_st[q * 4 + 2] = v.z; b_st[q * 4 + 3] = v.w;
                }
            } else {
#pragma unroll
                for (int j = 0; j < NPT; j++) b_st[j] = 0.f;
            }
        }
    };
    auto store_tile = [&](int p) {
#pragma unroll
        for (int j = 0; j < 8; j++)
            Ap[p][ak + j][am] = split_tf32(a_st[j]);
        if (TRANSB) {
#pragma unroll
            for (int j = 0; j < KTILE / 2; j++)
                Bp[p][bkT + j][bnT] = split_tf32(b_st[j]);
        } else {
#pragma unroll
            for (int j = 0; j < NPT; j++)
                Bp[p][bkN][bnN + j] = split_tf32(b_st[j]);
        }
    };

    float acc[MT][4][4] = {};

    load_tile(0);
    store_tile(0);
    __syncthreads();
    int p = 0;
    for (int kt = 0; kt < KT; kt++) {
        if (kt + 1 < KT) load_tile(kt + 1);

#pragma unroll
        for (int ks = 0; ks < KTILE; ks += 8) {
            // B fragments (shared across all m-tiles)
            uint32_t bh[4][2], bl[4][2];
#pragma unroll
            for (int nt = 0; nt < 4; nt++) {
                int nb = wn + nt * 8 + fg;
                uint2 v0 = Bp[p][ks + fc    ][nb];
                uint2 v1 = Bp[p][ks + fc + 4][nb];
                bh[nt][0] = v0.x; bl[nt][0] = v0.y;
                bh[nt][1] = v1.x; bl[nt][1] = v1.y;
            }
#pragma unroll
            for (int mt = 0; mt < MT; mt++) {
                int mb = wm + mt * 16 + fg;
                uint32_t ah[4], al[4];
                uint2 v;
                v = Ap[p][ks + fc    ][mb];     ah[0] = v.x; al[0] = v.y;
                v = Ap[p][ks + fc    ][mb + 8]; ah[1] = v.x; al[1] = v.y;
                v = Ap[p][ks + fc + 4][mb];     ah[2] = v.x; al[2] = v.y;
                v = Ap[p][ks + fc + 4][mb + 8]; ah[3] = v.x; al[3] = v.y;
#pragma unroll
                for (int nt = 0; nt < 4; nt++) {
                    mma_tf32(acc[mt][nt], ah, bh[nt]);
                    mma_tf32(acc[mt][nt], ah, bl[nt]);
                    mma_tf32(acc[mt][nt], al, bh[nt]);
                }
            }
        }

        if (kt + 1 < KT) {
            store_tile(p ^ 1);
            __syncthreads();
            p ^= 1;
        }
    }

    // epilogue
#pragma unroll
    for (int mt = 0; mt < MT; mt++) {
#pragma unroll
        for (int nt = 0; nt < 4; nt++) {
            int n0 = bn + wn + nt * 8 + fc * 2;
#pragma unroll
            for (int half = 0; half < 2; half++) {
                int m = bm + wm + mt * 16 + fg + half * 8;
                float v0 = acc[mt][nt][half * 2];
                float v1 = acc[mt][nt][half * 2 + 1];
                if (MASKED) {
                    v0 = (n0     >= NH_ + m) ? -INFINITY : v0 * SCALE_;
                    v1 = (n0 + 1 >= NH_ + m) ? -INFINITY : v1 * SCALE_;
                } else {
                    if (bias) { v0 += bias[n0]; v1 += bias[n0 + 1]; }
                    if (RELU) { v0 = fmaxf(v0, 0.f); v1 = fmaxf(v1, 0.f); }
                    if (RESADD) {
                        float2 rr = *(const float2*)(res + (size_t)m * ldc + n0);
                        v0 += rr.x; v1 += rr.y;
                    }
                }
                *(float2*)(C + (size_t)m * ldc + n0) = make_float2(v0, v1);
            }
        }
    }
}

// ---------------- softmax over W (row-wise, handles -inf tail) ----------------
__global__ void softmax_rows() {
    const int row = blockIdx.x;  // B*H*NV
    float* p = g_scores + (size_t)row * W_;
    const int t = threadIdx.x;   // 128
    float vals[6];
    float m = -INFINITY;
#pragma unroll
    for (int i = 0; i < 6; i++) { vals[i] = p[t + i * 128]; m = fmaxf(m, vals[i]); }
    __shared__ float red[128];
    red[t] = m; __syncthreads();
    for (int s = 64; s > 0; s >>= 1) { if (t < s) red[t] = fmaxf(red[t], red[t + s]); __syncthreads(); }
    m = red[0];
    __syncthreads();
    float sum = 0.f;
#pragma unroll
    for (int i = 0; i < 6; i++) { vals[i] = __expf(vals[i] - m); sum += vals[i]; }
    red[t] = sum; __syncthreads();
    for (int s = 64; s > 0; s >>= 1) { if (t < s) red[t] += red[t + s]; __syncthreads(); }
    float inv = 1.f / red[0];
#pragma unroll
    for (int i = 0; i < 6; i++) p[t + i * 128] = vals[i] * inv;
}

// ---------------- layernorm: out = g * norm(base + delta) + beta ----------------
__global__ void ln_kernel(const float* __restrict__ base, const float* __restrict__ delta,
                          const float* __restrict__ gamma, const float* __restrict__ beta,
                          float* __restrict__ out) {
    const int row = blockIdx.x;  // B*NV
    const int t = threadIdx.x;   // 256
    const float* br = base + (size_t)row * HA_;
    float x0 = br[t];
    float x1 = br[t + 256];
    if (delta) {
        const float* dr = delta + (size_t)row * HA_;
        x0 += dr[t];
        x1 += dr[t + 256];
    }
    __shared__ float red[256];
    red[t] = x0 + x1; __syncthreads();
    for (int s = 128; s > 0; s >>= 1) { if (t < s) red[t] += red[t + s]; __syncthreads(); }
    float mean = red[0] * (1.f / HA_);
    __syncthreads();
    float d0 = x0 - mean, d1 = x1 - mean;
    red[t] = d0 * d0 + d1 * d1; __syncthreads();
    for (int s = 128; s > 0; s >>= 1) { if (t < s) red[t] += red[t + s]; __syncthreads(); }
    float inv = rsqrtf(red[0] * (1.f / HA_) + EPS_);
    out[(size_t)row * HA_ + t]       = gamma[t]       * (d0 * inv) + beta[t];
    out[(size_t)row * HA_ + t + 256] = gamma[t + 256] * (d1 * inv) + beta[t + 256];
}

// ---------------- final loss reduction (deterministic, one CTA per batch) ----------------
__global__ void loss_kernel(const float* __restrict__ pu, float* __restrict__ out) {
    const int b = blockIdx.x;
    const int t = threadIdx.x;           // 256 = 8 warps
    const int warp = t >> 5, lane = t & 31;
    const float LOG_R = logf((float)R_);
    float accum = 0.f;
    for (int v = 1 + warp; v < NV_; v += 8) {
        const float* lr = g_logits + ((size_t)(b * NV_ + v)) * R_;
        float lv[4];
        float m = -INFINITY;
#pragma unroll
        for (int i = 0; i < 4; i++) { lv[i] = lr[lane + i * 32]; m = fmaxf(m, lv[i]); }
#pragma unroll
        for (int o = 16; o > 0; o >>= 1) m = fmaxf(m, __shfl_xor_sync(0xffffffffu, m, o));
        float se = 0.f;
#pragma unroll
        for (int i = 0; i < 4; i++) se += expf(lv[i] - m);
#pragma unroll
        for (int o = 16; o > 0; o >>= 1) se += __shfl_xor_sync(0xffffffffu, se, o);
        if (lane == 0) {
            float lse = m + logf(se);
            int tgt = (int)floorf(pu[b * NV_ + v] * (float)R_);
            tgt = min(max(tgt, 0), R_ - 1);
            accum += lse - lr[tgt] - LOG_R;
        }
    }
    __shared__ float red[8];
    if (lane == 0) red[warp] = accum;
    __syncthreads();
    if (t == 0) {
        float s = 0.f;
#pragma unroll
        for (int i = 0; i < 8; i++) s += red[i];
        out[b] = s;
    }
}

// ---------------- host launch ----------------
static float* sym_addr(const void* sym) {
    void* p = nullptr;
    cudaGetSymbolAddress(&p, sym);
    return (float*)p;
}

extern "C" void kernel_launch(void* const* d_in, const int* in_sizes, int n_in,
                              void* d_out, int out_size) {
    (void)in_sizes; (void)n_in; (void)out_size;
    const float* hist  = (const float*)d_in[0];
    const float* hu    = (const float*)d_in[1];
    const float* pred  = (const float*)d_in[2];
    const float* pu    = (const float*)d_in[3];
    const float* ds_w  = (const float*)d_in[4];
    const float* ds_b  = (const float*)d_in[5];
    const float* key_w = (const float*)d_in[6];
    const float* key_b = (const float*)d_in[7];
    const float* val_w = (const float*)d_in[8];
    const float* val_b = (const float*)d_in[9];
    const float* ln1_g = (const float*)d_in[10];
    const float* ln1_b = (const float*)d_in[11];
    const float* ln2_g = (const float*)d_in[12];
    const float* ln2_b = (const float*)d_in[13];
    const float* ff_w1 = (const float*)d_in[14];
    const float* ff_b1 = (const float*)d_in[15];
    const float* ff_w2 = (const float*)d_in[16];
    const float* ff_b2 = (const float*)d_in[17];
    const float* ff_w3 = (const float*)d_in[18];
    const float* ff_b3 = (const float*)d_in[19];
    const float* de_w  = (const float*)d_in[20];
    const float* de_b  = (const float*)d_in[21];
    float* out = (float*)d_out;

    float* ki    = sym_addr(g_ki);
    float* kwT   = sym_addr(g_kwT);
    float* vwT   = sym_addr(g_vwT);
    float* att   = sym_addr(g_att);
    float* keys  = sym_addr(g_keys);
    float* vals  = sym_addr(g_vals);
    float* scr   = sym_addr(g_scores);
    float* res   = sym_addr(g_res);
    float* ff1   = sym_addr(g_ff1);
    float* ff2   = sym_addr(g_ff2);
    float* logit = sym_addr(g_logits);

    const int BNV = B_ * NV_;          // 4096
    const int BW  = B_ * W_;           // 12288

    // 1. inputs
    {
        int total = B_ * W_ * KI_LD_;
        build_ki<<<(total + 255) / 256, 256>>>(hist, hu, pred, pu);
    }
    {
        int total = (D_ + 1) * GHA_;
        transpose_w<<<(total + 255) / 256, 256>>>(key_w, kwT);
        transpose_w<<<(total + 255) / 256, 256>>>(val_w, vwT);
    }
    // 2. att = pred @ ds_w + ds_b   [4096, 512] K=256   (64-row tiles: 512 CTAs)
    gemm_tc<64, 16, false, false, false, false, false><<<dim3(HA_ / 64, BNV / 64, 1), 128>>>(
        pred, ds_w, ds_b, nullptr, att, HA_, D_, D_, HA_, HA_,
        0, 0, 0, 0, 0, 0, 1);
    // 3. keys / vals = ki @ kwT + bias  [12288, 2048] K=257 (128-row tiles: 3072 CTAs)
    gemm_tc<128, 8, false, false, false, false, false><<<dim3(GHA_ / 64, BW / 128, 1), 128>>>(
        ki, kwT, key_b, nullptr, keys, GHA_, D_ + 1, KI_LD_, GHA_, GHA_,
        0, 0, 0, 0, 0, 0, 1);
    gemm_tc<128, 8, false, false, false, false, false><<<dim3(GHA_ / 64, BW / 128, 1), 128>>>(
        ki, vwT, val_b, nullptr, vals, GHA_, D_ + 1, KI_LD_, GHA_, GHA_,
        0, 0, 0, 0, 0, 0, 1);

    const long long sQ1  = (long long)NV_ * HA_;      // per-b stride of att
    const long long sKV1 = (long long)W_ * GHA_;      // per-b stride of keys/vals
    const long long sS   = (long long)NV_ * W_;       // per-(b,h) stride of scores
    const long long sO1  = (long long)NV_ * HA_;      // per-b stride of res/att

    // 4. layers
    for (int l = 0; l < L_; l++) {
        // scores[b,h,v,w] = mask(-inf) or scale * Q.K   (batched z = b*8+h)
        gemm_tc<128, 8, true, true, false, false, false><<<dim3(W_ / 64, NV_ / 128, B_ * H_), 128>>>(
            att, keys + l * H_ * A_, nullptr, nullptr, scr,
            W_, A_, HA_, GHA_, W_,
            sQ1, (long long)A_, sKV1, (long long)A_, 8 * sS, sS, H_);
        softmax_rows<<<B_ * H_ * NV_, 128>>>();
        // res = att + P @ V  (batched, K trimmed to causal bound; 64-row tiles)
        gemm_tc<64, 16, false, false, false, true, true><<<dim3(1, NV_ / 64, B_ * H_), 128>>>(
            scr, vals + l * H_ * A_, nullptr, att, res,
            A_, W_, W_, GHA_, HA_,
            8 * sS, sS, sKV1, (long long)A_, sO1, (long long)A_, H_);
        ln_kernel<<<BNV, 256>>>(res, nullptr, ln1_g + l * HA_, ln1_b + l * HA_, att);
        gemm_tc<64, 16, false, false, true, false, false><<<dim3(M_ / 64, BNV / 64, 1), 128>>>(
            att, ff_w1 + (size_t)l * HA_ * M_, ff_b1 + l * M_, nullptr, ff1,
            M_, HA_, HA_, M_, M_, 0, 0, 0, 0, 0, 0, 1);
        gemm_tc<64, 16, false, false, true, false, false><<<dim3(M_ / 64, BNV / 64, 1), 128>>>(
            ff1, ff_w2 + (size_t)l * M_ * M_, ff_b2 + l * M_, nullptr, ff2,
            M_, M_, M_, M_, M_, 0, 0, 0, 0, 0, 0, 1);
        gemm_tc<64, 16, false, false, false, false, false><<<dim3(HA_ / 64, BNV / 64, 1), 128>>>(
            ff2, ff_w3 + (size_t)l * M_ * HA_, ff_b3 + l * HA_, nullptr, res,
            HA_, M_, M_, HA_, HA_, 0, 0, 0, 0, 0, 0, 1);
        ln_kernel<<<BNV, 256>>>(att, res, ln2_g + l * HA_, ln2_b + l * HA_, att);
    }
    // 5. logits + loss
    gemm_tc<64, 16, false, false, false, false, false><<<dim3(R_ / 64, BNV / 64, 1), 128>>>(
        att, de_w, de_b, nullptr, logit, R_, HA_, HA_, R_, R_,
        0, 0, 0, 0, 0, 0, 1);
    loss_kernel<<<B_, 256>>>(pu, out);
}

// round 7
// speedup vs baseline: 2.2555x; 1.5876x over previous
#include <cuda_runtime.h>
#include <cuda_bf16.h>
#include <math.h>
#include <stdint.h>

// ---------------- problem constants ----------------
constexpr int B_  = 16;
constexpr int D_  = 256;
constexpr int NH_ = 512;
constexpr int NV_ = 256;
constexpr int W_  = 768;          // NH + NV
constexpr int L_  = 4;
constexpr int H_  = 8;
constexpr int A_  = 64;
constexpr int HA_ = 512;
constexpr int M_  = 512;
constexpr int R_  = 128;
constexpr int GHA_ = L_ * H_ * A_;   // 2048
constexpr int KI_LD_ = 260;          // padded ki stride (16B-aligned rows)
constexpr float EPS_   = 1e-5f;
constexpr float SCALE_ = 0.125f;     // A^-0.5

// ---------------- device scratch (no allocs allowed) ----------------
__device__ float g_ki   [B_ * W_ * KI_LD_];
__device__ float g_kwT  [(D_ + 1) * GHA_];
__device__ float g_vwT  [(D_ + 1) * GHA_];
__device__ float g_att  [B_ * NV_ * HA_];
__device__ float g_keys [(size_t)B_ * W_ * GHA_];
__device__ float g_vals [(size_t)B_ * W_ * GHA_];
__device__ float g_scores[(size_t)B_ * H_ * NV_ * W_];
__device__ float g_res  [B_ * NV_ * HA_];
__device__ float g_ff1  [B_ * NV_ * M_];
__device__ float g_ff2  [B_ * NV_ * M_];
__device__ float g_logits[B_ * NV_ * R_];

// ---------------- build ki = [hist||u ; pred||u]  [B, W, 260(pad)] ----------------
__global__ void build_ki(const float* __restrict__ hist, const float* __restrict__ hu,
                         const float* __restrict__ pred, const float* __restrict__ pu) {
    int idx = blockIdx.x * blockDim.x + threadIdx.x;
    const int total = B_ * W_ * KI_LD_;
    if (idx >= total) return;
    int d = idx % KI_LD_;
    int w = (idx / KI_LD_) % W_;
    int b = idx / (KI_LD_ * W_);
    float v;
    if (d < D_) {
        v = (w < NH_) ? hist[((size_t)(b * NH_ + w)) * D_ + d]
                      : pred[((size_t)(b * NV_ + (w - NH_))) * D_ + d];
    } else if (d == D_) {
        v = (w < NH_) ? hu[b * NH_ + w] : pu[b * NV_ + (w - NH_)];
    } else {
        v = 0.f;
    }
    g_ki[idx] = v;
}

// key_w [L,H,257,A] -> [257, L*H*A]
__global__ void transpose_w(const float* __restrict__ src, float* __restrict__ dst) {
    int idx = blockIdx.x * blockDim.x + threadIdx.x;
    const int total = (D_ + 1) * GHA_;
    if (idx >= total) return;
    int c = idx % GHA_;
    int d = idx / GHA_;
    int g = c >> 6;        // l*H + h
    int a = c & 63;
    dst[idx] = src[((size_t)(g * (D_ + 1) + d)) * A_ + a];
}

// ---------------- bf16 split helpers ----------------
// pack two consecutive-k floats into (hi-pair, lo-pair) bf16x2 words
__device__ __forceinline__ uint2 split_bf16_pair(float x0, float x1) {
    __nv_bfloat162 h = __floats2bfloat162_rn(x0, x1);
    float2 hf = __bfloat1622float2(h);
    __nv_bfloat162 l = __floats2bfloat162_rn(x0 - hf.x, x1 - hf.y);
    uint2 r;
    r.x = *reinterpret_cast<uint32_t*>(&h);
    r.y = *reinterpret_cast<uint32_t*>(&l);
    return r;
}

__device__ __forceinline__ void mma_bf16(float (&d)[4], const uint32_t (&a)[4],
                                         const uint32_t (&b)[2]) {
    asm volatile(
        "mma.sync.aligned.m16n8k16.row.col.f32.bf16.bf16.f32 "
        "{%0,%1,%2,%3},{%4,%5,%6,%7},{%8,%9},{%0,%1,%2,%3};"
        : "+f"(d[0]), "+f"(d[1]), "+f"(d[2]), "+f"(d[3])
        : "r"(a[0]), "r"(a[1]), "r"(a[2]), "r"(a[3]), "r"(b[0]), "r"(b[1]));
}

// ======================================================================
// Tensor-core GEMM, 3xBF16 split (acc += hi*hi + hi*lo + lo*hi), ~fp32-
// level accuracy (dropped lo*lo ~ 2^-18/product). KTILE=16 (m16n8k16).
// CTA: 128 threads, tile BM(m) x 64(n); 4 warps as 2(m) x 2(n);
// SMEM holds (hi-pair, lo-pair) uint2 per (k-pair, col) -> LDS.64 frags.
// Batched via blockIdx.z with composite (z/Hdiv, z%Hdiv) strides.
// ======================================================================
template <int BM, bool TRANSB, bool MASKED, bool RELU, bool KTRIM, bool RESADD>
__global__ __launch_bounds__(128, 4)
void gemm_tc(const float* __restrict__ A, const float* __restrict__ Bm,
             const float* __restrict__ bias, const float* __restrict__ resid,
             float* __restrict__ C,
             int N, int K, int lda, int ldb, int ldc,
             long long sA1, long long sA2, long long sB1, long long sB2,
             long long sC1, long long sC2, int Hdiv)
{
    constexpr int MT  = BM / 32;            // mtiles per warp
    constexpr int APF = (BM == 128) ? 8 : 4; // A k-pairs per thread
    const int z = blockIdx.z;
    const long long zq = z / Hdiv, zr = z % Hdiv;
    A  += zq * sA1 + zr * sA2;
    Bm += zq * sB1 + zr * sB2;
    const long long coff = zq * sC1 + zr * sC2;
    C += coff;
    const float* res = RESADD ? (resid + coff) : nullptr;

    const int bm = blockIdx.y * BM;
    const int bn = blockIdx.x * 64;
    const int t    = threadIdx.x;
    const int lane = t & 31;
    const int warp = t >> 5;
    const int wm = (warp >> 1) * (BM / 2);   // warp m offset
    const int wn = (warp & 1) * 32;          // warp n offset
    const int fc = lane & 3;
    const int fg = lane >> 2;

    if (MASKED && bn >= NH_ + bm + BM) {
        float2 ninf = make_float2(-INFINITY, -INFINITY);
#pragma unroll
        for (int mt = 0; mt < MT; mt++) {
            int m0 = bm + wm + mt * 16 + fg;
#pragma unroll
            for (int nt = 0; nt < 4; nt++) {
                int n0 = bn + wn + nt * 8 + fc * 2;
                *(float2*)(C + (size_t)m0 * ldc + n0) = ninf;
                *(float2*)(C + (size_t)(m0 + 8) * ldc + n0) = ninf;
            }
        }
        return;
    }

    __shared__ uint2 Ap[2][8][BM + 4];   // [buf][k-pair][m]
    __shared__ uint2 Bp[2][8][68];       // [buf][k-pair][n]

    int Kuse = KTRIM ? min(K, NH_ + bm + BM) : K;
    const int KT = (Kuse + 15) >> 4;

    // A loader
    const int am   = (BM == 128) ? t : (t >> 1);
    const int aoff = (BM == 128) ? 0 : (t & 1) * 8;   // k offset within tile
    // B non-trans loader: k-pair row, 4 consecutive n
    const int kpB = t >> 4, nB = (t & 15) * 4;
    // B trans loader: col n, 8 consecutive k
    const int nT = t >> 1, koT = (t & 1) * 8;

    float a_st[2 * APF], b_st[8];

    auto load_tile = [&](int kt) {
        const int k0 = kt << 4;
        const float* arow = A + (size_t)(bm + am) * lda + k0 + aoff;
        if (k0 + aoff + 2 * APF <= Kuse) {
#pragma unroll
            for (int q = 0; q < APF / 2; q++) {
                float4 v = *(const float4*)(arow + q * 4);
                a_st[q * 4 + 0] = v.x; a_st[q * 4 + 1] = v.y;
                a_st[q * 4 + 2] = v.z; a_st[q * 4 + 3] = v.w;
            }
        } else {
#pragma unroll
            for (int j = 0; j < 2 * APF; j++)
                a_st[j] = (k0 + aoff + j < Kuse) ? arow[j] : 0.f;
        }
        if (TRANSB) {
            const float* brow = Bm + (size_t)(bn + nT) * ldb + k0 + koT;
            if (k0 + koT + 8 <= Kuse) {
                float4 v0 = *(const float4*)(brow);
                float4 v1 = *(const float4*)(brow + 4);
                b_st[0] = v0.x; b_st[1] = v0.y; b_st[2] = v0.z; b_st[3] = v0.w;
                b_st[4] = v1.x; b_st[5] = v1.y; b_st[6] = v1.z; b_st[7] = v1.w;
            } else {
#pragma unroll
                for (int j = 0; j < 8; j++)
                    b_st[j] = (k0 + koT + j < Kuse) ? brow[j] : 0.f;
            }
        } else {
            int r0 = k0 + 2 * kpB, r1 = r0 + 1;
            float4 v0, v1;
            if (r0 < Kuse) v0 = *(const float4*)(Bm + (size_t)r0 * ldb + bn + nB);
            else           v0 = make_float4(0.f, 0.f, 0.f, 0.f);
            if (r1 < Kuse) v1 = *(const float4*)(Bm + (size_t)r1 * ldb + bn + nB);
            else           v1 = make_float4(0.f, 0.f, 0.f, 0.f);
            b_st[0] = v0.x; b_st[1] = v1.x;
            b_st[2] = v0.y; b_st[3] = v1.y;
            b_st[4] = v0.z; b_st[5] = v1.z;
            b_st[6] = v0.w; b_st[7] = v1.w;
        }
    };
    auto store_tile = [&](int p) {
        const int akp0 = aoff >> 1;
#pragma unroll
        for (int j = 0; j < APF; j++)
            Ap[p][akp0 + j][am] = split_bf16_pair(a_st[2 * j], a_st[2 * j + 1]);
        if (TRANSB) {
            const int kp0 = koT >> 1;
#pragma unroll
            for (int j = 0; j < 4; j++)
                Bp[p][kp0 + j][nT] = split_bf16_pair(b_st[2 * j], b_st[2 * j + 1]);
        } else {
#pragma unroll
            for (int j = 0; j < 4; j++)
                Bp[p][kpB][nB + j] = split_bf16_pair(b_st[2 * j], b_st[2 * j + 1]);
        }
    };

    float acc[MT][4][4] = {};

    load_tile(0);
    store_tile(0);
    __syncthreads();
    int p = 0;
    for (int kt = 0; kt < KT; kt++) {
        if (kt + 1 < KT) load_tile(kt + 1);

        // B fragments (shared across m-tiles)
        uint32_t bh[4][2], bl[4][2];
#pragma unroll
        for (int nt = 0; nt < 4; nt++) {
            int nb = wn + nt * 8 + fg;
            uint2 v0 = Bp[p][fc    ][nb];
            uint2 v1 = Bp[p][fc + 4][nb];
            bh[nt][0] = v0.x; bl[nt][0] = v0.y;
            bh[nt][1] = v1.x; bl[nt][1] = v1.y;
        }
#pragma unroll
        for (int mt = 0; mt < MT; mt++) {
            int mb = wm + mt * 16 + fg;
            uint32_t ah[4], al[4];
            uint2 v;
            v = Ap[p][fc    ][mb];     ah[0] = v.x; al[0] = v.y;
            v = Ap[p][fc    ][mb + 8]; ah[1] = v.x; al[1] = v.y;
            v = Ap[p][fc + 4][mb];     ah[2] = v.x; al[2] = v.y;
            v = Ap[p][fc + 4][mb + 8]; ah[3] = v.x; al[3] = v.y;
#pragma unroll
            for (int nt = 0; nt < 4; nt++) {
                mma_bf16(acc[mt][nt], ah, bh[nt]);
                mma_bf16(acc[mt][nt], ah, bl[nt]);
                mma_bf16(acc[mt][nt], al, bh[nt]);
            }
        }

        if (kt + 1 < KT) {
            store_tile(p ^ 1);
            __syncthreads();
            p ^= 1;
        }
    }

    // epilogue
#pragma unroll
    for (int mt = 0; mt < MT; mt++) {
#pragma unroll
        for (int nt = 0; nt < 4; nt++) {
            int n0 = bn + wn + nt * 8 + fc * 2;
#pragma unroll
            for (int half = 0; half < 2; half++) {
                int m = bm + wm + mt * 16 + fg + half * 8;
                float v0 = acc[mt][nt][half * 2];
                float v1 = acc[mt][nt][half * 2 + 1];
                if (MASKED) {
                    v0 = (n0     >= NH_ + m) ? -INFINITY : v0 * SCALE_;
                    v1 = (n0 + 1 >= NH_ + m) ? -INFINITY : v1 * SCALE_;
                } else {
                    if (bias) { v0 += bias[n0]; v1 += bias[n0 + 1]; }
                    if (RELU) { v0 = fmaxf(v0, 0.f); v1 = fmaxf(v1, 0.f); }
                    if (RESADD) {
                        float2 rr = *(const float2*)(res + (size_t)m * ldc + n0);
                        v0 += rr.x; v1 += rr.y;
                    }
                }
                *(float2*)(C + (size_t)m * ldc + n0) = make_float2(v0, v1);
            }
        }
    }
}

// ---------------- softmax over W (row-wise, handles -inf tail) ----------------
__global__ void softmax_rows() {
    const int row = blockIdx.x;  // B*H*NV
    float* p = g_scores + (size_t)row * W_;
    const int t = threadIdx.x;   // 128
    float vals[6];
    float m = -INFINITY;
#pragma unroll
    for (int i = 0; i < 6; i++) { vals[i] = p[t + i * 128]; m = fmaxf(m, vals[i]); }
    __shared__ float red[128];
    red[t] = m; __syncthreads();
    for (int s = 64; s > 0; s >>= 1) { if (t < s) red[t] = fmaxf(red[t], red[t + s]); __syncthreads(); }
    m = red[0];
    __syncthreads();
    float sum = 0.f;
#pragma unroll
    for (int i = 0; i < 6; i++) { vals[i] = __expf(vals[i] - m); sum += vals[i]; }
    red[t] = sum; __syncthreads();
    for (int s = 64; s > 0; s >>= 1) { if (t < s) red[t] += red[t + s]; __syncthreads(); }
    float inv = 1.f / red[0];
#pragma unroll
    for (int i = 0; i < 6; i++) p[t + i * 128] = vals[i] * inv;
}

// ---------------- layernorm: out = g * norm(base + delta) + beta ----------------
__global__ void ln_kernel(const float* __restrict__ base, const float* __restrict__ delta,
                          const float* __restrict__ gamma, const float* __restrict__ beta,
                          float* __restrict__ out) {
    const int row = blockIdx.x;  // B*NV
    const int t = threadIdx.x;   // 256
    const float* br = base + (size_t)row * HA_;
    float x0 = br[t];
    float x1 = br[t + 256];
    if (delta) {
        const float* dr = delta + (size_t)row * HA_;
        x0 += dr[t];
        x1 += dr[t + 256];
    }
    __shared__ float red[256];
    red[t] = x0 + x1; __syncthreads();
    for (int s = 128; s > 0; s >>= 1) { if (t < s) red[t] += red[t + s]; __syncthreads(); }
    float mean = red[0] * (1.f / HA_);
    __syncthreads();
    float d0 = x0 - mean, d1 = x1 - mean;
    red[t] = d0 * d0 + d1 * d1; __syncthreads();
    for (int s = 128; s > 0; s >>= 1) { if (t < s) red[t] += red[t + s]; __syncthreads(); }
    float inv = rsqrtf(red[0] * (1.f / HA_) + EPS_);
    out[(size_t)row * HA_ + t]       = gamma[t]       * (d0 * inv) + beta[t];
    out[(size_t)row * HA_ + t + 256] = gamma[t + 256] * (d1 * inv) + beta[t + 256];
}

// ---------------- final loss reduction (deterministic, one CTA per batch) ----------------
__global__ void loss_kernel(const float* __restrict__ pu, float* __restrict__ out) {
    const int b = blockIdx.x;
    const int t = threadIdx.x;           // 256 = 8 warps
    const int warp = t >> 5, lane = t & 31;
    const float LOG_R = logf((float)R_);
    float accum = 0.f;
    for (int v = 1 + warp; v < NV_; v += 8) {
        const float* lr = g_logits + ((size_t)(b * NV_ + v)) * R_;
        float lv[4];
        float m = -INFINITY;
#pragma unroll
        for (int i = 0; i < 4; i++) { lv[i] = lr[lane + i * 32]; m = fmaxf(m, lv[i]); }
#pragma unroll
        for (int o = 16; o > 0; o >>= 1) m = fmaxf(m, __shfl_xor_sync(0xffffffffu, m, o));
        float se = 0.f;
#pragma unroll
        for (int i = 0; i < 4; i++) se += expf(lv[i] - m);
#pragma unroll
        for (int o = 16; o > 0; o >>= 1) se += __shfl_xor_sync(0xffffffffu, se, o);
        if (lane == 0) {
            float lse = m + logf(se);
            int tgt = (int)floorf(pu[b * NV_ + v] * (float)R_);
            tgt = min(max(tgt, 0), R_ - 1);
            accum += lse - lr[tgt] - LOG_R;
        }
    }
    __shared__ float red[8];
    if (lane == 0) red[warp] = accum;
    __syncthreads();
    if (t == 0) {
        float s = 0.f;
#pragma unroll
        for (int i = 0; i < 8; i++) s += red[i];
        out[b] = s;
    }
}

// ---------------- host launch ----------------
static float* sym_addr(const void* sym) {
    void* p = nullptr;
    cudaGetSymbolAddress(&p, sym);
    return (float*)p;
}

extern "C" void kernel_launch(void* const* d_in, const int* in_sizes, int n_in,
                              void* d_out, int out_size) {
    (void)in_sizes; (void)n_in; (void)out_size;
    const float* hist  = (const float*)d_in[0];
    const float* hu    = (const float*)d_in[1];
    const float* pred  = (const float*)d_in[2];
    const float* pu    = (const float*)d_in[3];
    const float* ds_w  = (const float*)d_in[4];
    const float* ds_b  = (const float*)d_in[5];
    const float* key_w = (const float*)d_in[6];
    const float* key_b = (const float*)d_in[7];
    const float* val_w = (const float*)d_in[8];
    const float* val_b = (const float*)d_in[9];
    const float* ln1_g = (const float*)d_in[10];
    const float* ln1_b = (const float*)d_in[11];
    const float* ln2_g = (const float*)d_in[12];
    const float* ln2_b = (const float*)d_in[13];
    const float* ff_w1 = (const float*)d_in[14];
    const float* ff_b1 = (const float*)d_in[15];
    const float* ff_w2 = (const float*)d_in[16];
    const float* ff_b2 = (const float*)d_in[17];
    const float* ff_w3 = (const float*)d_in[18];
    const float* ff_b3 = (const float*)d_in[19];
    const float* de_w  = (const float*)d_in[20];
    const float* de_b  = (const float*)d_in[21];
    float* out = (float*)d_out;

    float* ki    = sym_addr(g_ki);
    float* kwT   = sym_addr(g_kwT);
    float* vwT   = sym_addr(g_vwT);
    float* att   = sym_addr(g_att);
    float* keys  = sym_addr(g_keys);
    float* vals  = sym_addr(g_vals);
    float* scr   = sym_addr(g_scores);
    float* res   = sym_addr(g_res);
    float* ff1   = sym_addr(g_ff1);
    float* ff2   = sym_addr(g_ff2);
    float* logit = sym_addr(g_logits);

    const int BNV = B_ * NV_;          // 4096
    const int BW  = B_ * W_;           // 12288

    // 1. inputs
    {
        int total = B_ * W_ * KI_LD_;
        build_ki<<<(total + 255) / 256, 256>>>(hist, hu, pred, pu);
    }
    {
        int total = (D_ + 1) * GHA_;
        transpose_w<<<(total + 255) / 256, 256>>>(key_w, kwT);
        transpose_w<<<(total + 255) / 256, 256>>>(val_w, vwT);
    }
    // 2. att = pred @ ds_w + ds_b   [4096, 512] K=256
    gemm_tc<64, false, false, false, false, false><<<dim3(HA_ / 64, BNV / 64, 1), 128>>>(
        pred, ds_w, ds_b, nullptr, att, HA_, D_, D_, HA_, HA_,
        0, 0, 0, 0, 0, 0, 1);
    // 3. keys / vals = ki @ kwT + bias  [12288, 2048] K=257
    gemm_tc<128, false, false, false, false, false><<<dim3(GHA_ / 64, BW / 128, 1), 128>>>(
        ki, kwT, key_b, nullptr, keys, GHA_, D_ + 1, KI_LD_, GHA_, GHA_,
        0, 0, 0, 0, 0, 0, 1);
    gemm_tc<128, false, false, false, false, false><<<dim3(GHA_ / 64, BW / 128, 1), 128>>>(
        ki, vwT, val_b, nullptr, vals, GHA_, D_ + 1, KI_LD_, GHA_, GHA_,
        0, 0, 0, 0, 0, 0, 1);

    const long long sQ1  = (long long)NV_ * HA_;      // per-b stride of att
    const long long sKV1 = (long long)W_ * GHA_;      // per-b stride of keys/vals
    const long long sS   = (long long)NV_ * W_;       // per-(b,h) stride of scores
    const long long sO1  = (long long)NV_ * HA_;      // per-b stride of res/att

    // 4. layers
    for (int l = 0; l < L_; l++) {
        // scores[b,h,v,w] = mask(-inf) or scale * Q.K   (batched z = b*8+h)
        gemm_tc<128, true, true, false, false, false><<<dim3(W_ / 64, NV_ / 128, B_ * H_), 128>>>(
            att, keys + l * H_ * A_, nullptr, nullptr, scr,
            W_, A_, HA_, GHA_, W_,
            sQ1, (long long)A_, sKV1, (long long)A_, 8 * sS, sS, H_);
        softmax_rows<<<B_ * H_ * NV_, 128>>>();
        // res = att + P @ V  (batched, K trimmed to causal bound)
        gemm_tc<64, false, false, false, true, true><<<dim3(1, NV_ / 64, B_ * H_), 128>>>(
            scr, vals + l * H_ * A_, nullptr, att, res,
            A_, W_, W_, GHA_, HA_,
            8 * sS, sS, sKV1, (long long)A_, sO1, (long long)A_, H_);
        ln_kernel<<<BNV, 256>>>(res, nullptr, ln1_g + l * HA_, ln1_b + l * HA_, att);
        gemm_tc<64, false, false, true, false, false><<<dim3(M_ / 64, BNV / 64, 1), 128>>>(
            att, ff_w1 + (size_t)l * HA_ * M_, ff_b1 + l * M_, nullptr, ff1,
            M_, HA_, HA_, M_, M_, 0, 0, 0, 0, 0, 0, 1);
        gemm_tc<64, false, false, true, false, false><<<dim3(M_ / 64, BNV / 64, 1), 128>>>(
            ff1, ff_w2 + (size_t)l * M_ * M_, ff_b2 + l * M_, nullptr, ff2,
            M_, M_, M_, M_, M_, 0, 0, 0, 0, 0, 0, 1);
        gemm_tc<64, false, false, false, false, false><<<dim3(HA_ / 64, BNV / 64, 1), 128>>>(
            ff2, ff_w3 + (size_t)l * M_ * HA_, ff_b3 + l * HA_, nullptr, res,
            HA_, M_, M_, HA_, HA_, 0, 0, 0, 0, 0, 0, 1);
        ln_kernel<<<BNV, 256>>>(att, res, ln2_g + l * HA_, ln2_b + l * HA_, att);
    }
    // 5. logits + loss
    gemm_tc<64, false, false, false, false, false><<<dim3(R_ / 64, BNV / 64, 1), 128>>>(
        att, de_w, de_b, nullptr, logit, R_, HA_, HA_, R_, R_,
        0, 0, 0, 0, 0, 0, 1);
    loss_kernel<<<B_, 256>>>(pu, out);
}

// round 8
// speedup vs baseline: 2.3720x; 1.0516x over previous
#include <cuda_runtime.h>
#include <cuda_bf16.h>
#include <math.h>
#include <stdint.h>

// ---------------- problem constants ----------------
constexpr int B_  = 16;
constexpr int D_  = 256;
constexpr int NH_ = 512;
constexpr int NV_ = 256;
constexpr int W_  = 768;          // NH + NV
constexpr int L_  = 4;
constexpr int H_  = 8;
constexpr int A_  = 64;
constexpr int HA_ = 512;
constexpr int M_  = 512;
constexpr int R_  = 128;
constexpr int GHA_ = L_ * H_ * A_;   // 2048
constexpr int KI_LD_ = 260;          // padded ki stride (16B-aligned rows)
constexpr float EPS_   = 1e-5f;
constexpr float SCALE_ = 0.125f;     // A^-0.5

// ---------------- device scratch (no allocs allowed) ----------------
__device__ float g_ki   [B_ * W_ * KI_LD_];
__device__ float g_kwT  [(D_ + 1) * GHA_];
__device__ float g_vwT  [(D_ + 1) * GHA_];
__device__ float g_att  [B_ * NV_ * HA_];
__device__ float g_keys [(size_t)B_ * W_ * GHA_];
__device__ float g_vals [(size_t)B_ * W_ * GHA_];
__device__ float g_res  [B_ * NV_ * HA_];
__device__ float g_ff1  [B_ * NV_ * M_];
__device__ float g_ff2  [B_ * NV_ * M_];
__device__ float g_logits[B_ * NV_ * R_];

// ---------------- build ki = [hist||u ; pred||u]  [B, W, 260(pad)] ----------------
__global__ void build_ki(const float* __restrict__ hist, const float* __restrict__ hu,
                         const float* __restrict__ pred, const float* __restrict__ pu) {
    int idx = blockIdx.x * blockDim.x + threadIdx.x;
    const int total = B_ * W_ * KI_LD_;
    if (idx >= total) return;
    int d = idx % KI_LD_;
    int w = (idx / KI_LD_) % W_;
    int b = idx / (KI_LD_ * W_);
    float v;
    if (d < D_) {
        v = (w < NH_) ? hist[((size_t)(b * NH_ + w)) * D_ + d]
                      : pred[((size_t)(b * NV_ + (w - NH_))) * D_ + d];
    } else if (d == D_) {
        v = (w < NH_) ? hu[b * NH_ + w] : pu[b * NV_ + (w - NH_)];
    } else {
        v = 0.f;
    }
    g_ki[idx] = v;
}

// key_w [L,H,257,A] -> [257, L*H*A]
__global__ void transpose_w(const float* __restrict__ src, float* __restrict__ dst) {
    int idx = blockIdx.x * blockDim.x + threadIdx.x;
    const int total = (D_ + 1) * GHA_;
    if (idx >= total) return;
    int c = idx % GHA_;
    int d = idx / GHA_;
    int g = c >> 6;        // l*H + h
    int a = c & 63;
    dst[idx] = src[((size_t)(g * (D_ + 1) + d)) * A_ + a];
}

// ---------------- bf16 split helpers ----------------
__device__ __forceinline__ uint2 split_bf16_pair(float x0, float x1) {
    __nv_bfloat162 h = __floats2bfloat162_rn(x0, x1);
    float2 hf = __bfloat1622float2(h);
    __nv_bfloat162 l = __floats2bfloat162_rn(x0 - hf.x, x1 - hf.y);
    uint2 r;
    r.x = *reinterpret_cast<uint32_t*>(&h);
    r.y = *reinterpret_cast<uint32_t*>(&l);
    return r;
}

__device__ __forceinline__ void mma_bf16(float (&d)[4], const uint32_t (&a)[4],
                                         const uint32_t (&b)[2]) {
    asm volatile(
        "mma.sync.aligned.m16n8k16.row.col.f32.bf16.bf16.f32 "
        "{%0,%1,%2,%3},{%4,%5,%6,%7},{%8,%9},{%0,%1,%2,%3};"
        : "+f"(d[0]), "+f"(d[1]), "+f"(d[2]), "+f"(d[3])
        : "r"(a[0]), "r"(a[1]), "r"(a[2]), "r"(a[3]), "r"(b[0]), "r"(b[1]));
}

// ======================================================================
// Tensor-core GEMM, 3xBF16 split. (unchanged engine from R7)
// ======================================================================
template <int BM, bool TRANSB, bool MASKED, bool RELU, bool KTRIM, bool RESADD>
__global__ __launch_bounds__(128, 4)
void gemm_tc(const float* __restrict__ A, const float* __restrict__ Bm,
             const float* __restrict__ bias, const float* __restrict__ resid,
             float* __restrict__ C,
             int N, int K, int lda, int ldb, int ldc,
             long long sA1, long long sA2, long long sB1, long long sB2,
             long long sC1, long long sC2, int Hdiv)
{
    constexpr int MT  = BM / 32;
    constexpr int APF = (BM == 128) ? 8 : 4;
    const int z = blockIdx.z;
    const long long zq = z / Hdiv, zr = z % Hdiv;
    A  += zq * sA1 + zr * sA2;
    Bm += zq * sB1 + zr * sB2;
    const long long coff = zq * sC1 + zr * sC2;
    C += coff;
    const float* res = RESADD ? (resid + coff) : nullptr;

    const int bm = blockIdx.y * BM;
    const int bn = blockIdx.x * 64;
    const int t    = threadIdx.x;
    const int lane = t & 31;
    const int warp = t >> 5;
    const int wm = (warp >> 1) * (BM / 2);
    const int wn = (warp & 1) * 32;
    const int fc = lane & 3;
    const int fg = lane >> 2;

    if (MASKED && bn >= NH_ + bm + BM) {
        float2 ninf = make_float2(-INFINITY, -INFINITY);
#pragma unroll
        for (int mt = 0; mt < MT; mt++) {
            int m0 = bm + wm + mt * 16 + fg;
#pragma unroll
            for (int nt = 0; nt < 4; nt++) {
                int n0 = bn + wn + nt * 8 + fc * 2;
                *(float2*)(C + (size_t)m0 * ldc + n0) = ninf;
                *(float2*)(C + (size_t)(m0 + 8) * ldc + n0) = ninf;
            }
        }
        return;
    }

    __shared__ uint2 Ap[2][8][BM + 4];
    __shared__ uint2 Bp[2][8][68];

    int Kuse = KTRIM ? min(K, NH_ + bm + BM) : K;
    const int KT = (Kuse + 15) >> 4;

    const int am   = (BM == 128) ? t : (t >> 1);
    const int aoff = (BM == 128) ? 0 : (t & 1) * 8;
    const int kpB = t >> 4, nB = (t & 15) * 4;
    const int nT = t >> 1, koT = (t & 1) * 8;

    float a_st[2 * APF], b_st[8];

    auto load_tile = [&](int kt) {
        const int k0 = kt << 4;
        const float* arow = A + (size_t)(bm + am) * lda + k0 + aoff;
        if (k0 + aoff + 2 * APF <= Kuse) {
#pragma unroll
            for (int q = 0; q < APF / 2; q++) {
                float4 v = *(const float4*)(arow + q * 4);
                a_st[q * 4 + 0] = v.x; a_st[q * 4 + 1] = v.y;
                a_st[q * 4 + 2] = v.z; a_st[q * 4 + 3] = v.w;
            }
        } else {
#pragma unroll
            for (int j = 0; j < 2 * APF; j++)
                a_st[j] = (k0 + aoff + j < Kuse) ? arow[j] : 0.f;
        }
        if (TRANSB) {
            const float* brow = Bm + (size_t)(bn + nT) * ldb + k0 + koT;
            if (k0 + koT + 8 <= Kuse) {
                float4 v0 = *(const float4*)(brow);
                float4 v1 = *(const float4*)(brow + 4);
                b_st[0] = v0.x; b_st[1] = v0.y; b_st[2] = v0.z; b_st[3] = v0.w;
                b_st[4] = v1.x; b_st[5] = v1.y; b_st[6] = v1.z; b_st[7] = v1.w;
            } else {
#pragma unroll
                for (int j = 0; j < 8; j++)
                    b_st[j] = (k0 + koT + j < Kuse) ? brow[j] : 0.f;
            }
        } else {
            int r0 = k0 + 2 * kpB, r1 = r0 + 1;
            float4 v0, v1;
            if (r0 < Kuse) v0 = *(const float4*)(Bm + (size_t)r0 * ldb + bn + nB);
            else           v0 = make_float4(0.f, 0.f, 0.f, 0.f);
            if (r1 < Kuse) v1 = *(const float4*)(Bm + (size_t)r1 * ldb + bn + nB);
            else           v1 = make_float4(0.f, 0.f, 0.f, 0.f);
            b_st[0] = v0.x; b_st[1] = v1.x;
            b_st[2] = v0.y; b_st[3] = v1.y;
            b_st[4] = v0.z; b_st[5] = v1.z;
            b_st[6] = v0.w; b_st[7] = v1.w;
        }
    };
    auto store_tile = [&](int p) {
        const int akp0 = aoff >> 1;
#pragma unroll
        for (int j = 0; j < APF; j++)
            Ap[p][akp0 + j][am] = split_bf16_pair(a_st[2 * j], a_st[2 * j + 1]);
        if (TRANSB) {
            const int kp0 = koT >> 1;
#pragma unroll
            for (int j = 0; j < 4; j++)
                Bp[p][kp0 + j][nT] = split_bf16_pair(b_st[2 * j], b_st[2 * j + 1]);
        } else {
#pragma unroll
            for (int j = 0; j < 4; j++)
                Bp[p][kpB][nB + j] = split_bf16_pair(b_st[2 * j], b_st[2 * j + 1]);
        }
    };

    float acc[MT][4][4] = {};

    load_tile(0);
    store_tile(0);
    __syncthreads();
    int p = 0;
    for (int kt = 0; kt < KT; kt++) {
        if (kt + 1 < KT) load_tile(kt + 1);

        uint32_t bh[4][2], bl[4][2];
#pragma unroll
        for (int nt = 0; nt < 4; nt++) {
            int nb = wn + nt * 8 + fg;
            uint2 v0 = Bp[p][fc    ][nb];
            uint2 v1 = Bp[p][fc + 4][nb];
            bh[nt][0] = v0.x; bl[nt][0] = v0.y;
            bh[nt][1] = v1.x; bl[nt][1] = v1.y;
        }
#pragma unroll
        for (int mt = 0; mt < MT; mt++) {
            int mb = wm + mt * 16 + fg;
            uint32_t ah[4], al[4];
            uint2 v;
            v = Ap[p][fc    ][mb];     ah[0] = v.x; al[0] = v.y;
            v = Ap[p][fc    ][mb + 8]; ah[1] = v.x; al[1] = v.y;
            v = Ap[p][fc + 4][mb];     ah[2] = v.x; al[2] = v.y;
            v = Ap[p][fc + 4][mb + 8]; ah[3] = v.x; al[3] = v.y;
#pragma unroll
            for (int nt = 0; nt < 4; nt++) {
                mma_bf16(acc[mt][nt], ah, bh[nt]);
                mma_bf16(acc[mt][nt], ah, bl[nt]);
                mma_bf16(acc[mt][nt], al, bh[nt]);
            }
        }

        if (kt + 1 < KT) {
            store_tile(p ^ 1);
            __syncthreads();
            p ^= 1;
        }
    }

#pragma unroll
    for (int mt = 0; mt < MT; mt++) {
#pragma unroll
        for (int nt = 0; nt < 4; nt++) {
            int n0 = bn + wn + nt * 8 + fc * 2;
#pragma unroll
            for (int half = 0; half < 2; half++) {
                int m = bm + wm + mt * 16 + fg + half * 8;
                float v0 = acc[mt][nt][half * 2];
                float v1 = acc[mt][nt][half * 2 + 1];
                if (MASKED) {
                    v0 = (n0     >= NH_ + m) ? -INFINITY : v0 * SCALE_;
                    v1 = (n0 + 1 >= NH_ + m) ? -INFINITY : v1 * SCALE_;
                } else {
                    if (bias) { v0 += bias[n0]; v1 += bias[n0 + 1]; }
                    if (RELU) { v0 = fmaxf(v0, 0.f); v1 = fmaxf(v1, 0.f); }
                    if (RESADD) {
                        float2 rr = *(const float2*)(res + (size_t)m * ldc + n0);
                        v0 += rr.x; v1 += rr.y;
                    }
                }
                *(float2*)(C + (size_t)m * ldc + n0) = make_float2(v0, v1);
            }
        }
    }
}

// ======================================================================
// Fused flash attention: res = att + softmax(mask(Q.K^T)*scale) @ V
// Grid (NV/64, B*H), 128 threads (4 warps: 2(m) x 2(w-slice)).
// Q tile 64x64 resident in smem; K/V tiles streamed; online softmax;
// P re-split to bf16 hi/lo in regs; all matmuls 3xBF16.
// Dynamic smem: Qs(17408) + Ks(17408) + Vs(17408) + red(1024) = 53248.
// Osum (64x64 f32 = 16384) overlays Ks after the main loop.
// ======================================================================
constexpr int FA_SMEM = 3 * 17408 + 1024;

__global__ __launch_bounds__(128, 3)
void fa_kernel(const float* __restrict__ Qg, const float* __restrict__ Kg,
               const float* __restrict__ Vg, float* __restrict__ Rg, int l)
{
    const int vt = blockIdx.x;
    const int bh = blockIdx.y;
    const int b = bh >> 3, h = bh & 7;
    const int t = threadIdx.x;
    const int lane = t & 31, warp = t >> 5;
    const int wm = (warp >> 1) * 32;     // warp row offset
    const int wc = warp & 1;             // warp w-slice
    const int wn = wc * 32;
    const int fc = lane & 3, fg = lane >> 2;

    extern __shared__ char smraw[];
    uint2* Qs = (uint2*)smraw;                        // [32][68] (a-pair, row)
    uint2* Ks = (uint2*)(smraw + 17408);              // [32][68] (a-pair, w)
    uint2* Vs = (uint2*)(smraw + 2 * 17408);          // [32][68] (w-pair, j)
    float* redM = (float*)(smraw + 3 * 17408);        // [64][2]
    float* redS = redM + 128;                         // [64][2]
    float* Osum = (float*)(smraw + 17408);            // overlays Ks

    const float* qbase = Qg + ((size_t)(b * NV_ + vt * 64)) * HA_ + h * A_;
    const size_t kvoff = (size_t)(l * H_ + h) * A_;
    const float* kbase = Kg + (size_t)b * W_ * GHA_ + kvoff;
    const float* vbase = Vg + (size_t)b * W_ * GHA_ + kvoff;

    // load Q tile once (rows 64 x a 64), split to bf16 hi/lo
    {
        int r = t >> 1, aoff = (t & 1) * 32;
        const float* src = qbase + (size_t)r * HA_ + aoff;
#pragma unroll
        for (int q = 0; q < 8; q++) {
            float4 v = *(const float4*)(src + q * 4);
            int kp = (aoff >> 1) + q * 2;
            Qs[kp * 68 + r]       = split_bf16_pair(v.x, v.y);
            Qs[(kp + 1) * 68 + r] = split_bf16_pair(v.z, v.w);
        }
    }

    float O[2][8][4] = {};
    float s_m[4], s_l[4];
#pragma unroll
    for (int i = 0; i < 4; i++) { s_m[i] = -INFINITY; s_l[i] = 0.f; }

    const int ntiles = vt + 9;
    for (int wt = 0; wt < ntiles; wt++) {
        __syncthreads();   // previous tile's Ks/Vs readers done
        // load K tile [w 64][a 64] -> Ks[a_pair][w]
        {
            int w = t >> 1, aoff = (t & 1) * 32;
            const float* src = kbase + (size_t)(wt * 64 + w) * GHA_ + aoff;
#pragma unroll
            for (int q = 0; q < 8; q++) {
                float4 v = *(const float4*)(src + q * 4);
                int kp = (aoff >> 1) + q * 2;
                Ks[kp * 68 + w]       = split_bf16_pair(v.x, v.y);
                Ks[(kp + 1) * 68 + w] = split_bf16_pair(v.z, v.w);
            }
        }
        // load V tile [w 64][j 64] -> Vs[w_pair][j]
        {
            int wp = t >> 2, jb = (t & 3) * 16;
            const float* s0 = vbase + (size_t)(wt * 64 + 2 * wp) * GHA_ + jb;
            const float* s1 = s0 + GHA_;
#pragma unroll
            for (int q = 0; q < 4; q++) {
                float4 v0 = *(const float4*)(s0 + q * 4);
                float4 v1 = *(const float4*)(s1 + q * 4);
                Vs[wp * 68 + jb + q * 4 + 0] = split_bf16_pair(v0.x, v1.x);
                Vs[wp * 68 + jb + q * 4 + 1] = split_bf16_pair(v0.y, v1.y);
                Vs[wp * 68 + jb + q * 4 + 2] = split_bf16_pair(v0.z, v1.z);
                Vs[wp * 68 + jb + q * 4 + 3] = split_bf16_pair(v0.w, v1.w);
            }
        }
        __syncthreads();

        // scores: s = Q . K^T  (64x64 per CTA, warp does 32(m) x 32(w))
        float s[2][4][4] = {};
#pragma unroll
        for (int kc = 0; kc < 4; kc++) {
            uint32_t ah[2][4], al[2][4];
#pragma unroll
            for (int mt = 0; mt < 2; mt++) {
                int mr = wm + mt * 16 + fg;
                uint2 q0 = Qs[(kc * 8 + fc) * 68 + mr];
                uint2 q1 = Qs[(kc * 8 + fc) * 68 + mr + 8];
                uint2 q2 = Qs[(kc * 8 + fc + 4) * 68 + mr];
                uint2 q3 = Qs[(kc * 8 + fc + 4) * 68 + mr + 8];
                ah[mt][0] = q0.x; ah[mt][1] = q1.x; ah[mt][2] = q2.x; ah[mt][3] = q3.x;
                al[mt][0] = q0.y; al[mt][1] = q1.y; al[mt][2] = q2.y; al[mt][3] = q3.y;
            }
#pragma unroll
            for (int nt = 0; nt < 4; nt++) {
                int nc = wn + nt * 8 + fg;
                uint2 k0 = Ks[(kc * 8 + fc) * 68 + nc];
                uint2 k1 = Ks[(kc * 8 + fc + 4) * 68 + nc];
                uint32_t bh[2] = {k0.x, k1.x}, bl[2] = {k0.y, k1.y};
#pragma unroll
                for (int mt = 0; mt < 2; mt++) {
                    mma_bf16(s[mt][nt], ah[mt], bh);
                    mma_bf16(s[mt][nt], ah[mt], bl);
                    mma_bf16(s[mt][nt], al[mt], bh);
                }
            }
        }

        // scale + mask (only last tile can be masked) + thread-local row max
        const bool mtile = (wt == vt + 8);
        float mx[4];
#pragma unroll
        for (int i = 0; i < 4; i++) mx[i] = -INFINITY;
#pragma unroll
        for (int mt = 0; mt < 2; mt++)
#pragma unroll
            for (int nt = 0; nt < 4; nt++)
#pragma unroll
                for (int c = 0; c < 4; c++) {
                    float v = s[mt][nt][c] * SCALE_;
                    if (mtile) {
                        int wg = wt * 64 + wn + nt * 8 + fc * 2 + (c & 1);
                        int vg = vt * 64 + wm + mt * 16 + fg + (c >> 1) * 8;
                        if (wg >= NH_ + vg) v = -INFINITY;
                    }
                    s[mt][nt][c] = v;
                    int i = mt * 2 + (c >> 1);
                    mx[i] = fmaxf(mx[i], v);
                }
#pragma unroll
        for (int i = 0; i < 4; i++) {
            mx[i] = fmaxf(mx[i], __shfl_xor_sync(0xffffffffu, mx[i], 1));
            mx[i] = fmaxf(mx[i], __shfl_xor_sync(0xffffffffu, mx[i], 2));
        }
        if (fc == 0) {
#pragma unroll
            for (int i = 0; i < 4; i++)
                redM[(wm + (i >> 1) * 16 + fg + (i & 1) * 8) * 2 + wc] = mx[i];
        }
        __syncthreads();

        float mnew[4], alpha[4], sum[4];
#pragma unroll
        for (int i = 0; i < 4; i++) {
            int row = wm + (i >> 1) * 16 + fg + (i & 1) * 8;
            float tm = fmaxf(redM[row * 2], redM[row * 2 + 1]);
            mnew[i] = fmaxf(s_m[i], tm);
            alpha[i] = __expf(s_m[i] - mnew[i]);
            s_m[i] = mnew[i];
            sum[i] = 0.f;
        }
#pragma unroll
        for (int mt = 0; mt < 2; mt++)
#pragma unroll
            for (int nt = 0; nt < 4; nt++)
#pragma unroll
                for (int c = 0; c < 4; c++) {
                    int i = mt * 2 + (c >> 1);
                    float p = __expf(s[mt][nt][c] - mnew[i]);
                    s[mt][nt][c] = p;
                    sum[i] += p;
                }
#pragma unroll
        for (int i = 0; i < 4; i++) {
            sum[i] += __shfl_xor_sync(0xffffffffu, sum[i], 1);
            sum[i] += __shfl_xor_sync(0xffffffffu, sum[i], 2);
        }
        if (fc == 0) {
#pragma unroll
            for (int i = 0; i < 4; i++)
                redS[(wm + (i >> 1) * 16 + fg + (i & 1) * 8) * 2 + wc] = sum[i];
        }
        __syncthreads();
#pragma unroll
        for (int i = 0; i < 4; i++) {
            int row = wm + (i >> 1) * 16 + fg + (i & 1) * 8;
            s_l[i] = s_l[i] * alpha[i] + redS[row * 2] + redS[row * 2 + 1];
        }

        // rescale running O
#pragma unroll
        for (int mt = 0; mt < 2; mt++)
#pragma unroll
            for (int ntj = 0; ntj < 8; ntj++)
#pragma unroll
                for (int c = 0; c < 4; c++)
                    O[mt][ntj][c] *= alpha[mt * 2 + (c >> 1)];

        // PV: P (this warp's 32 w-cols) @ V -> partial O
#pragma unroll
        for (int kc = 0; kc < 2; kc++) {
            uint32_t ph[2][4], pl[2][4];
#pragma unroll
            for (int mt = 0; mt < 2; mt++) {
                uint2 u;
                u = split_bf16_pair(s[mt][2 * kc][0], s[mt][2 * kc][1]);         ph[mt][0] = u.x; pl[mt][0] = u.y;
                u = split_bf16_pair(s[mt][2 * kc][2], s[mt][2 * kc][3]);         ph[mt][1] = u.x; pl[mt][1] = u.y;
                u = split_bf16_pair(s[mt][2 * kc + 1][0], s[mt][2 * kc + 1][1]); ph[mt][2] = u.x; pl[mt][2] = u.y;
                u = split_bf16_pair(s[mt][2 * kc + 1][2], s[mt][2 * kc + 1][3]); ph[mt][3] = u.x; pl[mt][3] = u.y;
            }
#pragma unroll
            for (int ntj = 0; ntj < 8; ntj++) {
                int nc = ntj * 8 + fg;
                uint2 v0 = Vs[((wn >> 1) + kc * 8 + fc) * 68 + nc];
                uint2 v1 = Vs[((wn >> 1) + kc * 8 + fc + 4) * 68 + nc];
                uint32_t bh[2] = {v0.x, v1.x}, bl[2] = {v0.y, v1.y};
#pragma unroll
                for (int mt = 0; mt < 2; mt++) {
                    mma_bf16(O[mt][ntj], ph[mt], bh);
                    mma_bf16(O[mt][ntj], ph[mt], bl);
                    mma_bf16(O[mt][ntj], pl[mt], bh);
                }
            }
        }
    }

    // combine the two w-slice partials (Osum overlays Ks) and write out
    __syncthreads();
    if (wc == 0) {
#pragma unroll
        for (int mt = 0; mt < 2; mt++)
#pragma unroll
            for (int ntj = 0; ntj < 8; ntj++)
#pragma unroll
                for (int c = 0; c < 4; c++) {
                    int row = wm + mt * 16 + fg + (c >> 1) * 8;
                    Osum[row * 64 + ntj * 8 + fc * 2 + (c & 1)] = O[mt][ntj][c];
                }
        if (fc == 0) {
#pragma unroll
            for (int i = 0; i < 4; i++) {
                int row = wm + (i >> 1) * 16 + fg + (i & 1) * 8;
                redM[row * 2] = 1.f / s_l[i];
            }
        }
    }
    __syncthreads();
    if (wc == 1) {
#pragma unroll
        for (int mt = 0; mt < 2; mt++)
#pragma unroll
            for (int ntj = 0; ntj < 8; ntj++)
#pragma unroll
                for (int c = 0; c < 4; c++) {
                    int row = wm + mt * 16 + fg + (c >> 1) * 8;
                    Osum[row * 64 + ntj * 8 + fc * 2 + (c & 1)] += O[mt][ntj][c];
                }
    }
    __syncthreads();
    {
        int r = t >> 1, jb = (t & 1) * 32;
        const float* arow = qbase + (size_t)r * HA_ + jb;
        float* orow = Rg + ((size_t)(b * NV_ + vt * 64 + r)) * HA_ + h * A_ + jb;
        float linv = redM[r * 2];
#pragma unroll
        for (int q = 0; q < 8; q++) {
            float4 a = *(const float4*)(arow + q * 4);
            float4 o;
            o.x = a.x + Osum[r * 64 + jb + q * 4 + 0] * linv;
            o.y = a.y + Osum[r * 64 + jb + q * 4 + 1] * linv;
            o.z = a.z + Osum[r * 64 + jb + q * 4 + 2] * linv;
            o.w = a.w + Osum[r * 64 + jb + q * 4 + 3] * linv;
            *(float4*)(orow + q * 4) = o;
        }
    }
}

// ---------------- layernorm: out = g * norm(base + delta) + beta ----------------
__global__ void ln_kernel(const float* __restrict__ base, const float* __restrict__ delta,
                          const float* __restrict__ gamma, const float* __restrict__ beta,
                          float* __restrict__ out) {
    const int row = blockIdx.x;  // B*NV
    const int t = threadIdx.x;   // 256
    const float* br = base + (size_t)row * HA_;
    float x0 = br[t];
    float x1 = br[t + 256];
    if (delta) {
        const float* dr = delta + (size_t)row * HA_;
        x0 += dr[t];
        x1 += dr[t + 256];
    }
    __shared__ float red[256];
    red[t] = x0 + x1; __syncthreads();
    for (int s = 128; s > 0; s >>= 1) { if (t < s) red[t] += red[t + s]; __syncthreads(); }
    float mean = red[0] * (1.f / HA_);
    __syncthreads();
    float d0 = x0 - mean, d1 = x1 - mean;
    red[t] = d0 * d0 + d1 * d1; __syncthreads();
    for (int s = 128; s > 0; s >>= 1) { if (t < s) red[t] += red[t + s]; __syncthreads(); }
    float inv = rsqrtf(red[0] * (1.f / HA_) + EPS_);
    out[(size_t)row * HA_ + t]       = gamma[t]       * (d0 * inv) + beta[t];
    out[(size_t)row * HA_ + t + 256] = gamma[t + 256] * (d1 * inv) + beta[t + 256];
}

// ---------------- final loss reduction ----------------
__global__ void loss_kernel(const float* __restrict__ pu, float* __restrict__ out) {
    const int b = blockIdx.x;
    const int t = threadIdx.x;           // 256 = 8 warps
    const int warp = t >> 5, lane = t & 31;
    const float LOG_R = logf((float)R_);
    float accum = 0.f;
    for (int v = 1 + warp; v < NV_; v += 8) {
        const float* lr = g_logits + ((size_t)(b * NV_ + v)) * R_;
        float lv[4];
        float m = -INFINITY;
#pragma unroll
        for (int i = 0; i < 4; i++) { lv[i] = lr[lane + i * 32]; m = fmaxf(m, lv[i]); }
#pragma unroll
        for (int o = 16; o > 0; o >>= 1) m = fmaxf(m, __shfl_xor_sync(0xffffffffu, m, o));
        float se = 0.f;
#pragma unroll
        for (int i = 0; i < 4; i++) se += expf(lv[i] - m);
#pragma unroll
        for (int o = 16; o > 0; o >>= 1) se += __shfl_xor_sync(0xffffffffu, se, o);
        if (lane == 0) {
            float lse = m + logf(se);
            int tgt = (int)floorf(pu[b * NV_ + v] * (float)R_);
            tgt = min(max(tgt, 0), R_ - 1);
            accum += lse - lr[tgt] - LOG_R;
        }
    }
    __shared__ float red[8];
    if (lane == 0) red[warp] = accum;
    __syncthreads();
    if (t == 0) {
        float s = 0.f;
#pragma unroll
        for (int i = 0; i < 8; i++) s += red[i];
        out[b] = s;
    }
}

// ---------------- host launch ----------------
static float* sym_addr(const void* sym) {
    void* p = nullptr;
    cudaGetSymbolAddress(&p, sym);
    return (float*)p;
}

extern "C" void kernel_launch(void* const* d_in, const int* in_sizes, int n_in,
                              void* d_out, int out_size) {
    (void)in_sizes; (void)n_in; (void)out_size;
    const float* hist  = (const float*)d_in[0];
    const float* hu    = (const float*)d_in[1];
    const float* pred  = (const float*)d_in[2];
    const float* pu    = (const float*)d_in[3];
    const float* ds_w  = (const float*)d_in[4];
    const float* ds_b  = (const float*)d_in[5];
    const float* key_w = (const float*)d_in[6];
    const float* key_b = (const float*)d_in[7];
    const float* val_w = (const float*)d_in[8];
    const float* val_b = (const float*)d_in[9];
    const float* ln1_g = (const float*)d_in[10];
    const float* ln1_b = (const float*)d_in[11];
    const float* ln2_g = (const float*)d_in[12];
    const float* ln2_b = (const float*)d_in[13];
    const float* ff_w1 = (const float*)d_in[14];
    const float* ff_b1 = (const float*)d_in[15];
    const float* ff_w2 = (const float*)d_in[16];
    const float* ff_b2 = (const float*)d_in[17];
    const float* ff_w3 = (const float*)d_in[18];
    const float* ff_b3 = (const float*)d_in[19];
    const float* de_w  = (const float*)d_in[20];
    const float* de_b  = (const float*)d_in[21];
    float* out = (float*)d_out;

    float* ki    = sym_addr(g_ki);
    float* kwT   = sym_addr(g_kwT);
    float* vwT   = sym_addr(g_vwT);
    float* att   = sym_addr(g_att);
    float* keys  = sym_addr(g_keys);
    float* vals  = sym_addr(g_vals);
    float* res   = sym_addr(g_res);
    float* ff1   = sym_addr(g_ff1);
    float* ff2   = sym_addr(g_ff2);
    float* logit = sym_addr(g_logits);

    static bool attr_done = false;
    if (!attr_done) {
        cudaFuncSetAttribute(fa_kernel, cudaFuncAttributeMaxDynamicSharedMemorySize, FA_SMEM);
        attr_done = true;
    }

    const int BNV = B_ * NV_;          // 4096
    const int BW  = B_ * W_;           // 12288

    // 1. inputs
    {
        int total = B_ * W_ * KI_LD_;
        build_ki<<<(total + 255) / 256, 256>>>(hist, hu, pred, pu);
    }
    {
        int total = (D_ + 1) * GHA_;
        transpose_w<<<(total + 255) / 256, 256>>>(key_w, kwT);
        transpose_w<<<(total + 255) / 256, 256>>>(val_w, vwT);
    }
    // 2. att = pred @ ds_w + ds_b   [4096, 512] K=256
    gemm_tc<64, false, false, false, false, false><<<dim3(HA_ / 64, BNV / 64, 1), 128>>>(
        pred, ds_w, ds_b, nullptr, att, HA_, D_, D_, HA_, HA_,
        0, 0, 0, 0, 0, 0, 1);
    // 3. keys / vals = ki @ kwT + bias  [12288, 2048] K=257
    gemm_tc<128, false, false, false, false, false><<<dim3(GHA_ / 64, BW / 128, 1), 128>>>(
        ki, kwT, key_b, nullptr, keys, GHA_, D_ + 1, KI_LD_, GHA_, GHA_,
        0, 0, 0, 0, 0, 0, 1);
    gemm_tc<128, false, false, false, false, false><<<dim3(GHA_ / 64, BW / 128, 1), 128>>>(
        ki, vwT, val_b, nullptr, vals, GHA_, D_ + 1, KI_LD_, GHA_, GHA_,
        0, 0, 0, 0, 0, 0, 1);

    // 4. layers
    for (int l = 0; l < L_; l++) {
        fa_kernel<<<dim3(NV_ / 64, B_ * H_), 128, FA_SMEM>>>(att, keys, vals, res, l);
        ln_kernel<<<BNV, 256>>>(res, nullptr, ln1_g + l * HA_, ln1_b + l * HA_, att);
        gemm_tc<64, false, false, true, false, false><<<dim3(M_ / 64, BNV / 64, 1), 128>>>(
            att, ff_w1 + (size_t)l * HA_ * M_, ff_b1 + l * M_, nullptr, ff1,
            M_, HA_, HA_, M_, M_, 0, 0, 0, 0, 0, 0, 1);
        gemm_tc<64, false, false, true, false, false><<<dim3(M_ / 64, BNV / 64, 1), 128>>>(
            ff1, ff_w2 + (size_t)l * M_ * M_, ff_b2 + l * M_, nullptr, ff2,
            M_, M_, M_, M_, M_, 0, 0, 0, 0, 0, 0, 1);
        gemm_tc<64, false, false, false, false, false><<<dim3(HA_ / 64, BNV / 64, 1), 128>>>(
            ff2, ff_w3 + (size_t)l * M_ * HA_, ff_b3 + l * HA_, nullptr, res,
            HA_, M_, M_, HA_, HA_, 0, 0, 0, 0, 0, 0, 1);
        ln_kernel<<<BNV, 256>>>(att, res, ln2_g + l * HA_, ln2_b + l * HA_, att);
    }
    // 5. logits + loss
    gemm_tc<64, false, false, false, false, false><<<dim3(R_ / 64, BNV / 64, 1), 128>>>(
        att, de_w, de_b, nullptr, logit, R_, HA_, HA_, R_, R_,
        0, 0, 0, 0, 0, 0, 1);
    loss_kernel<<<B_, 256>>>(pu, out);
}